// round 3
// baseline (speedup 1.0000x reference)
#include <cuda_runtime.h>
#include <cstdint>
#include <math.h>

#define NN 8746
#define KD 8746
#define HD 32
#define ZD 16
#define TT 6
#define EE 100000

// GEMM tiling: BM=64 rows/block, full K per block, 3-stage cp.async pipeline
#define BM 64
#define BK 32
#define NTILE ((KD + BK - 1) / BK)   // 274
#define ST 3
#define XS_STR 36            // padded row stride (floats)
#define WS_STR 40            // padded row stride (floats)

// scan: decoupled lookback
#define SCH 9                // chunks per timestep (9*1024 >= NN)

// ---------------- scratch (device globals; no allocations allowed) ----------
__device__ float d_h0[NN * HD];          // x @ W1
__device__ int   d_cnt[TT * NN];         // per-(t, dst) edge counts
__device__ int   d_off[TT * (NN + 1)];   // CSR offsets
__device__ int   d_cur[TT * NN];         // scatter cursors
__device__ int   d_sflag[TT * SCH];      // lookback flags (prefix+1), memset 0
__device__ int   d_srcb[TT * EE];        // CSR: source node
__device__ int   d_eidb[TT * EE];        // CSR: original edge index (dedup tiebreak)
__device__ float d_wb[TT * EE];          // CSR: edge weight (losers zeroed)
__device__ float d_diag[TT * NN];        // implicit diagonal value
__device__ float d_dinv[TT * NN];        // colsum^-0.5
__device__ float d_g[TT * NN * ZD];      // h @ W2
__device__ int   d_i64;                  // ei dtype flag (1 = int64)

// ---------------- helpers ---------------------------------------------------
__device__ __forceinline__ void cp8(uint32_t dst, const void* src, int nb) {
    asm volatile("cp.async.ca.shared.global [%0], [%1], 8, %2;\n"
                 :: "r"(dst), "l"(src), "r"(nb) : "memory");
}
__device__ __forceinline__ uint32_t f2tf(float f) {
    uint32_t r;
    asm("cvt.rna.tf32.f32 %0, %1;" : "=r"(r) : "f"(f));
    return r;
}
__device__ __forceinline__ int ld_idx(const int* ei, int pos, int f) {
    return f ? ei[2 * pos] : ei[pos];
}

// ---------------- dtype detect ----------------------------------------------
__global__ void detect_kernel(const int* __restrict__ ei) {
    if (threadIdx.x == 0 && blockIdx.x == 0) {
        d_i64 = (ei[1] == 0 && ei[3] == 0 && ei[5] == 0 && ei[7] == 0 && ei[9] == 0) ? 1 : 0;
    }
}

// ---------------- GEMM: h0 = x @ W1 (tf32 mma, full-K, 3-stage pipeline) -----
__global__ void __launch_bounds__(256, 2)
gemm_kernel(const float* __restrict__ x, const float* __restrict__ W1) {
    __shared__ __align__(16) float    xs[ST][BM * XS_STR];
    __shared__ __align__(16) uint32_t ws[ST][BK * WS_STR];

    const int tid  = threadIdx.x;
    const int lane = tid & 31;
    const int warp = tid >> 5;
    const int m0   = blockIdx.x * BM;

    float acc[2][4];
#pragma unroll
    for (int a = 0; a < 2; a++)
#pragma unroll
        for (int b = 0; b < 4; b++) acc[a][b] = 0.f;

    const uint32_t xs_base = (uint32_t)__cvta_generic_to_shared(&xs[0][0]);

    auto load_tiles = [&](int buf, int kb) {
        // W1 tile: BK k-rows x 32 cols, convert to tf32 at load
        {
            int kk = tid >> 3, g = tid & 7;
            int gk = kb + kk;
            float4 v = make_float4(0.f, 0.f, 0.f, 0.f);
            if (gk < KD) v = *reinterpret_cast<const float4*>(W1 + (size_t)gk * HD + g * 4);
            uint4 u;
            u.x = f2tf(v.x); u.y = f2tf(v.y); u.z = f2tf(v.z); u.w = f2tf(v.w);
            *reinterpret_cast<uint4*>(&ws[buf][kk * WS_STR + g * 4]) = u;
        }
        // x tile: 64 rows x 32 cols via 8B cp.async (x rows are 8B-aligned)
        uint32_t sb = xs_base + (uint32_t)buf * (BM * XS_STR * 4);
#pragma unroll
        for (int i = 0; i < 4; i++) {
            int f   = tid + 256 * i;      // 1024 chunks of 8B
            int row = f >> 4, g = f & 15;
            int gr  = m0 + row;
            int gc  = kb + g * 2;
            const float* src = x;
            int nb = 0;
            if (gr < NN && gc < KD) {
                src = x + (size_t)gr * KD + gc;
                nb  = min(2, KD - gc) * 4;
            }
            cp8(sb + (uint32_t)(row * XS_STR + g * 2) * 4, src, nb);
        }
    };

    // prologue: stages 0..ST-2
#pragma unroll
    for (int s = 0; s < ST - 1; s++) {
        load_tiles(s, s * BK);
        asm volatile("cp.async.commit_group;\n" ::: "memory");
    }

    const int arow  = (warp & 3) * 16 + (lane >> 2);
    const int nbase = (warp >> 2) * 16;
    const int kq    = lane & 3;

    for (int it = 0; it < NTILE; it++) {
        asm volatile("cp.async.wait_group %0;\n" :: "n"(ST - 2) : "memory");
        __syncthreads();

        // refill oldest buffer (consumed at it-1); commit unconditionally to
        // keep group indices aligned with tile indices
        if (it + ST - 1 < NTILE)
            load_tiles((it + ST - 1) % ST, (it + ST - 1) * BK);
        asm volatile("cp.async.commit_group;\n" ::: "memory");

        const float*    xb = xs[it % ST];
        const uint32_t* wb = ws[it % ST];
#pragma unroll
        for (int s = 0; s < 4; s++) {
            int k8 = s * 8;
            uint32_t a0 = f2tf(xb[arow * XS_STR + k8 + kq]);
            uint32_t a1 = f2tf(xb[(arow + 8) * XS_STR + k8 + kq]);
            uint32_t a2 = f2tf(xb[arow * XS_STR + k8 + 4 + kq]);
            uint32_t a3 = f2tf(xb[(arow + 8) * XS_STR + k8 + 4 + kq]);
#pragma unroll
            for (int nt = 0; nt < 2; nt++) {
                uint32_t b0 = wb[(k8 + kq) * WS_STR + nbase + nt * 8 + (lane >> 2)];
                uint32_t b1 = wb[(k8 + 4 + kq) * WS_STR + nbase + nt * 8 + (lane >> 2)];
                asm volatile(
                    "mma.sync.aligned.m16n8k8.row.col.f32.tf32.tf32.f32 "
                    "{%0,%1,%2,%3}, {%4,%5,%6,%7}, {%8,%9}, {%0,%1,%2,%3};\n"
                    : "+f"(acc[nt][0]), "+f"(acc[nt][1]), "+f"(acc[nt][2]), "+f"(acc[nt][3])
                    : "r"(a0), "r"(a1), "r"(a2), "r"(a3), "r"(b0), "r"(b1));
            }
        }
    }

    // direct store epilogue (no split-K, no atomics)
    const int r0 = m0 + (warp & 3) * 16 + (lane >> 2);
    const int r1 = r0 + 8;
    const int c0 = nbase + (lane & 3) * 2;
#pragma unroll
    for (int nt = 0; nt < 2; nt++) {
        int c = c0 + nt * 8;
        if (r0 < NN) {
            d_h0[r0 * HD + c]     = acc[nt][0];
            d_h0[r0 * HD + c + 1] = acc[nt][1];
        }
        if (r1 < NN) {
            d_h0[r1 * HD + c]     = acc[nt][2];
            d_h0[r1 * HD + c + 1] = acc[nt][3];
        }
    }
}

// ---------------- edge histogram --------------------------------------------
__global__ void hist_kernel(const int* __restrict__ ei) {
    int idx = blockIdx.x * 256 + threadIdx.x;
    if (idx >= TT * EE) return;
    int f = d_i64;
    int t = idx / EE, e = idx - t * EE;
    int j = ld_idx(ei, t * 2 * EE + EE + e, f);
    atomicAdd(&d_cnt[t * NN + j], 1);
}

// ---------------- scan: decoupled lookback, 54 resident blocks ---------------
__global__ void __launch_bounds__(1024) scan_kernel() {
    const int t   = blockIdx.y;
    const int ch  = blockIdx.x;
    const int tid = threadIdx.x;
    const int lane = tid & 31, w = tid >> 5;
    __shared__ int wsum[32];
    __shared__ int sh_prev, sh_total;

    int i = ch * 1024 + tid;
    int v = (i < NN) ? d_cnt[t * NN + i] : 0;

    // warp inclusive scan
    int incl = v;
#pragma unroll
    for (int o = 1; o < 32; o <<= 1) {
        int u = __shfl_up_sync(0xffffffffu, incl, o);
        if (lane >= o) incl += u;
    }
    if (lane == 31) wsum[w] = incl;
    __syncthreads();
    if (w == 0) {
        int s = wsum[lane];
        int is = s;
#pragma unroll
        for (int o = 1; o < 32; o <<= 1) {
            int u = __shfl_up_sync(0xffffffffu, is, o);
            if (lane >= o) is += u;
        }
        wsum[lane] = is - s;                 // exclusive warp offsets
        if (lane == 31) sh_total = is;       // block total
    }
    __syncthreads();
    int blk_incl = wsum[w] + incl;

    // lookback chain through L2
    if (tid == 0) {
        int prev = 0;
        if (ch > 0) {
            volatile int* vf = &d_sflag[t * SCH + ch - 1];
            int f;
            while ((f = *vf) == 0) { }
            __threadfence();
            prev = f - 1;
        }
        __threadfence();
        d_sflag[t * SCH + ch] = prev + sh_total + 1;   // publish ASAP
        sh_prev = prev;
    }
    __syncthreads();
    int prev = sh_prev;

    if (i < NN) {
        int excl = prev + blk_incl - v;
        d_off[t * (NN + 1) + i] = excl;
        d_cur[t * NN + i]       = excl;
    }
    if (ch == SCH - 1 && tid == 1023)
        d_off[t * (NN + 1) + NN] = prev + sh_total;
}

// ---------------- scatter edges into CSR (grouped by dst column) -------------
__global__ void scatter_kernel(const int* __restrict__ ei, const float* __restrict__ ew) {
    int idx = blockIdx.x * 256 + threadIdx.x;
    if (idx >= TT * EE) return;
    int f = d_i64;
    int t = idx / EE, e = idx - t * EE;
    int i = ld_idx(ei, t * 2 * EE + e, f);
    int j = ld_idx(ei, t * 2 * EE + EE + e, f);
    int pos = atomicAdd(&d_cur[t * NN + j], 1);
    d_srcb[t * EE + pos] = i;
    d_eidb[t * EE + pos] = e;
    d_wb[t * EE + pos]   = ew[idx];
}

// ---------------- dedup (last edge index wins) + degrees ---------------------
__global__ void __launch_bounds__(256) dedup_kernel() {
    int gw   = (blockIdx.x * 256 + threadIdx.x) >> 5;
    int lane = threadIdx.x & 31;
    if (gw >= TT * NN) return;
    int t = gw / NN, j = gw - t * NN;
    int beg = d_off[t * (NN + 1) + j];
    int end = d_off[t * (NN + 1) + j + 1];

    float sum = 0.f;
    int selfw = 0;
    for (int p = beg + lane; p < end; p += 32) {
        int src = d_srcb[t * EE + p];
        int eid = d_eidb[t * EE + p];
        bool win = true;
        for (int q = beg; q < end; q++) {
            if (d_srcb[t * EE + q] == src && d_eidb[t * EE + q] > eid) { win = false; break; }
        }
        if (win) {
            sum += d_wb[t * EE + p];
            if (src == j) selfw = 1;
        } else {
            d_wb[t * EE + p] = 0.f;
        }
    }
#pragma unroll
    for (int o = 16; o; o >>= 1) {
        sum   += __shfl_xor_sync(0xffffffffu, sum, o);
        selfw |= __shfl_xor_sync(0xffffffffu, selfw, o);
    }
    if (lane == 0) {
        float diag = selfw ? 0.f : 1.f;
        d_diag[t * NN + j] = diag;
        d_dinv[t * NN + j] = rsqrtf(diag + sum);
    }
}

// ---------------- SpMM1 + ReLU + (h @ W2) ------------------------------------
__global__ void __launch_bounds__(256) spmm1_kernel(const float* __restrict__ b1,
                                                    const float* __restrict__ W2) {
    __shared__ float hs[8][HD];
    int gw   = (blockIdx.x * 256 + threadIdx.x) >> 5;
    int lane = threadIdx.x & 31;
    int wib  = (threadIdx.x >> 5);
    if (gw >= TT * NN) return;
    int t = gw / NN, j = gw - t * NN;
    int beg = d_off[t * (NN + 1) + j];
    int end = d_off[t * (NN + 1) + j + 1];

    float dj  = d_dinv[t * NN + j];
    float acc = d_diag[t * NN + j] * dj * d_h0[j * HD + lane];
    for (int p = beg; p < end; p++) {
        int   src = d_srcb[t * EE + p];
        float w   = d_wb[t * EE + p];
        acc = fmaf(w * d_dinv[t * NN + src], d_h0[src * HD + lane], acc);
    }
    float h = fmaxf(fmaf(acc, dj, b1[lane]), 0.f);
    hs[wib][lane] = h;
    __syncwarp();
    if (lane < ZD) {
        float s = 0.f;
#pragma unroll
        for (int c = 0; c < HD; c++) s = fmaf(hs[wib][c], W2[c * ZD + lane], s);
        d_g[(size_t)gw * ZD + lane] = s;
    }
}

// ---------------- SpMM2 + tanh -> out (2 nodes per warp) ---------------------
__global__ void __launch_bounds__(256) spmm2_kernel(const float* __restrict__ b2,
                                                    float* __restrict__ out) {
    int gwarp = (blockIdx.x * 256 + threadIdx.x) >> 5;
    int lane  = threadIdx.x & 31;
    int half  = lane >> 4, k = lane & 15;
    int node  = gwarp * 2 + half;
    if (node >= TT * NN) return;
    int t = node / NN, j = node - t * NN;
    int beg = d_off[t * (NN + 1) + j];
    int end = d_off[t * (NN + 1) + j + 1];

    float dj  = d_dinv[t * NN + j];
    float acc = d_diag[t * NN + j] * dj * d_g[(size_t)node * ZD + k];
    for (int p = beg; p < end; p++) {
        int   src = d_srcb[t * EE + p];
        float w   = d_wb[t * EE + p];
        acc = fmaf(w * d_dinv[t * NN + src], d_g[(size_t)(t * NN + src) * ZD + k], acc);
    }
    out[(size_t)node * ZD + k] = tanhf(fmaf(acc, dj, b2[k]));
}

// ---------------- launch (single stream; gemm placed as launch #6 for ncu) ---
extern "C" void kernel_launch(void* const* d_in, const int* in_sizes, int n_in,
                              void* d_out, int out_size) {
    const float* x  = (const float*)d_in[0];
    const int*   ei = (const int*)d_in[1];
    const float* ew = (const float*)d_in[2];
    const float* W1 = (const float*)d_in[3];
    const float* b1 = (const float*)d_in[4];
    const float* W2 = (const float*)d_in[5];
    const float* b2 = (const float*)d_in[6];
    float* out = (float*)d_out;

    void *pcnt = nullptr, *pflag = nullptr;
    cudaGetSymbolAddress(&pcnt, d_cnt);
    cudaGetSymbolAddress(&pflag, d_sflag);
    cudaMemsetAsync(pcnt, 0, sizeof(int) * TT * NN);          // launch 1
    cudaMemsetAsync(pflag, 0, sizeof(int) * TT * SCH);        // launch 2

    detect_kernel<<<1, 32>>>(ei);                             // launch 3
    hist_kernel<<<(TT * EE + 255) / 256, 256>>>(ei);          // launch 4
    scan_kernel<<<dim3(SCH, TT), 1024>>>();                   // launch 5
    gemm_kernel<<<(NN + BM - 1) / BM, 256>>>(x, W1);          // launch 6 (profiled)
    scatter_kernel<<<(TT * EE + 255) / 256, 256>>>(ei, ew);   // launch 7
    dedup_kernel<<<(TT * NN * 32 + 255) / 256, 256>>>();      // launch 8
    spmm1_kernel<<<(TT * NN * 32 + 255) / 256, 256>>>(b1, W2);// launch 9
    spmm2_kernel<<<(TT * NN * 16 + 255) / 256, 256>>>(b2, out);// launch 10
}

// round 4
// speedup vs baseline: 1.6766x; 1.6766x over previous
#include <cuda_runtime.h>
#include <cstdint>
#include <math.h>

#define NN 8746
#define KD 8746
#define HD 32
#define ZD 16
#define TT 6
#define EE 100000

// GEMM tiling: BM=128, BK=32, split-K x7, 4-stage cp.async, 2 blocks/SM
#define BMg 128
#define BKg 32
#define STg 4
#define KSPLIT 7
#define TPC 40                         // tiles per K-chunk (last chunk: 34)
#define NTILE_TOT 274                  // ceil(8746/32)
#define XSTR 36                        // x row stride in floats = 9 x 16B
#define WSTR 40                        // W row stride in floats (conflict-free B reads)
#define XTILE_BYTES (BMg * XSTR * 4)   // 18432
#define WTILE_BYTES (BKg * WSTR * 4)   // 5120
#define GEMM_SMEM (STg * (XTILE_BYTES + WTILE_BYTES))   // 94208

// scan: decoupled lookback
#define SCH 9

// ---------------- scratch (device globals; no allocations allowed) ----------
__device__ float d_h0[NN * HD];
__device__ int   d_cnt[TT * NN];
__device__ int   d_off[TT * (NN + 1)];
__device__ int   d_cur[TT * NN];
__device__ int   d_sflag[TT * SCH];
__device__ int   d_srcb[TT * EE];
__device__ int   d_eidb[TT * EE];
__device__ float d_wb[TT * EE];
__device__ float d_diag[TT * NN];
__device__ float d_dinv[TT * NN];
__device__ float d_g[TT * NN * ZD];
__device__ int   d_i64;

// ---------------- helpers ---------------------------------------------------
__device__ __forceinline__ void cp16(uint32_t dst, const void* src, int nb) {
    asm volatile("cp.async.cg.shared.global [%0], [%1], 16, %2;\n"
                 :: "r"(dst), "l"(src), "r"(nb) : "memory");
}
__device__ __forceinline__ uint32_t f2tf(float f) {
    uint32_t r;
    asm("cvt.rna.tf32.f32 %0, %1;" : "=r"(r) : "f"(f));
    return r;
}
__device__ __forceinline__ int ld_idx(const int* ei, int pos, int f) {
    return f ? ei[2 * pos] : ei[pos];
}

// ---------------- dtype detect ----------------------------------------------
__global__ void detect_kernel(const int* __restrict__ ei) {
    if (threadIdx.x == 0 && blockIdx.x == 0) {
        d_i64 = (ei[1] == 0 && ei[3] == 0 && ei[5] == 0 && ei[7] == 0 && ei[9] == 0) ? 1 : 0;
    }
}

// ---------------- GEMM: h0 += x @ W1 (tf32 mma, split-K, 4-stage 16B pipe) ---
__global__ void __launch_bounds__(256, 2)
gemm_kernel(const float* __restrict__ x, const float* __restrict__ W1) {
    extern __shared__ __align__(16) char smem[];
    float* xs = (float*)smem;                              // [STg][BMg*XSTR]
    float* ws = (float*)(smem + STg * XTILE_BYTES);        // [STg][BKg*WSTR]

    const int tid  = threadIdx.x;
    const int lane = tid & 31;
    const int warp = tid >> 5;
    const int m0   = blockIdx.x * BMg;
    const int tile0 = blockIdx.y * TPC;
    const int ntile = min(TPC, NTILE_TOT - tile0);
    const int kbeg  = tile0 * BKg;
    const bool clampblk = (m0 + BMg > NN);
    const long XEND = (long)NN * KD;

    const uint32_t xs_u = (uint32_t)__cvta_generic_to_shared(xs);
    const uint32_t ws_u = (uint32_t)__cvta_generic_to_shared(ws);

    // per-thread x-copy slots: 128 rows x 9 chunks = 1152 slots
    long     xoff[5];
    uint32_t xdst[5];
    int      xnb0[5];
#pragma unroll
    for (int i = 0; i < 5; i++) {
        int s = tid + 256 * i;
        if (s < BMg * 9) {
            int row = s / 9, c = s - row * 9;
            int odd = row & 1;
            xoff[i] = (long)(m0 + row) * KD + kbeg + c * 4 - (odd ? 2 : 0);
            xdst[i] = (uint32_t)(row * XSTR + c * 4) * 4;
            xnb0[i] = (!odd && c == 8) ? 0 : 16;     // even rows: 8 chunks
        } else {
            xnb0[i] = -1;
        }
    }
    // W copy slot: 32 k-rows x 128B, 16B per thread
    const int wkk = tid >> 3, wg = tid & 7;
    const uint32_t wdst = (uint32_t)(wkk * WSTR + wg * 4) * 4;

    auto load_tiles = [&](int buf, int tileIdx) {
        const uint32_t xb = xs_u + (uint32_t)buf * XTILE_BYTES;
#pragma unroll
        for (int i = 0; i < 5; i++) {
            if (xnb0[i] >= 0) {
                long o = xoff[i] + (long)tileIdx * BKg;
                int nb = xnb0[i];
                if (clampblk) {
                    long remB = (XEND - o) * 4;
                    if (remB <= 0) { nb = 0; o = 0; }
                    else if (remB < nb) nb = (int)remB;
                }
                cp16(xb + xdst[i], x + o, nb);
            }
        }
        {
            int gk = kbeg + tileIdx * BKg + wkk;
            int nb = (gk < KD) ? 16 : 0;
            int ga = (gk < KD) ? gk : 0;
            cp16(ws_u + (uint32_t)buf * WTILE_BYTES + wdst,
                 W1 + (long)ga * HD + wg * 4, nb);
        }
    };

    // prologue: 3 stages
#pragma unroll
    for (int s = 0; s < STg - 1; s++) {
        load_tiles(s, s);
        asm volatile("cp.async.commit_group;\n" ::: "memory");
    }

    float acc[4][4];
#pragma unroll
    for (int a = 0; a < 4; a++)
#pragma unroll
        for (int b = 0; b < 4; b++) acc[a][b] = 0.f;

    const int arow = warp * 16 + (lane >> 2);
    const int sh   = (arow & 1) ? 2 : 0;       // parity shift (arow+8 same parity)
    const int kq   = lane & 3;
    const int qn   = lane >> 2;

    for (int it = 0; it < ntile; it++) {
        asm volatile("cp.async.wait_group %0;\n" :: "n"(STg - 2) : "memory");
        __syncthreads();

        if (it + STg - 1 < ntile)
            load_tiles((it + STg - 1) & 3, it + STg - 1);
        asm volatile("cp.async.commit_group;\n" ::: "memory");

        const float* xb = xs + (it & 3) * (BMg * XSTR);
        const float* wb = ws + (it & 3) * (BKg * WSTR);
#pragma unroll
        for (int s = 0; s < 4; s++) {
            const int k8 = s * 8;
            uint32_t a0 = f2tf(xb[arow * XSTR + sh + k8 + kq]);
            uint32_t a1 = f2tf(xb[(arow + 8) * XSTR + sh + k8 + kq]);
            uint32_t a2 = f2tf(xb[arow * XSTR + sh + k8 + 4 + kq]);
            uint32_t a3 = f2tf(xb[(arow + 8) * XSTR + sh + k8 + 4 + kq]);
#pragma unroll
            for (int nt = 0; nt < 4; nt++) {
                uint32_t b0 = f2tf(wb[(k8 + kq) * WSTR + nt * 8 + qn]);
                uint32_t b1 = f2tf(wb[(k8 + 4 + kq) * WSTR + nt * 8 + qn]);
                asm volatile(
                    "mma.sync.aligned.m16n8k8.row.col.f32.tf32.tf32.f32 "
                    "{%0,%1,%2,%3}, {%4,%5,%6,%7}, {%8,%9}, {%0,%1,%2,%3};\n"
                    : "+f"(acc[nt][0]), "+f"(acc[nt][1]), "+f"(acc[nt][2]), "+f"(acc[nt][3])
                    : "r"(a0), "r"(a1), "r"(a2), "r"(a3), "r"(b0), "r"(b1));
            }
        }
    }

    // split-K epilogue: atomic accumulate
    const int r0 = m0 + warp * 16 + (lane >> 2);
    const int r1 = r0 + 8;
    const int c0 = (lane & 3) * 2;
#pragma unroll
    for (int nt = 0; nt < 4; nt++) {
        int c = nt * 8 + c0;
        if (r0 < NN) {
            atomicAdd(&d_h0[r0 * HD + c],     acc[nt][0]);
            atomicAdd(&d_h0[r0 * HD + c + 1], acc[nt][1]);
        }
        if (r1 < NN) {
            atomicAdd(&d_h0[r1 * HD + c],     acc[nt][2]);
            atomicAdd(&d_h0[r1 * HD + c + 1], acc[nt][3]);
        }
    }
}

// ---------------- edge histogram --------------------------------------------
__global__ void hist_kernel(const int* __restrict__ ei) {
    int idx = blockIdx.x * 256 + threadIdx.x;
    if (idx >= TT * EE) return;
    int f = d_i64;
    int t = idx / EE, e = idx - t * EE;
    int j = ld_idx(ei, t * 2 * EE + EE + e, f);
    atomicAdd(&d_cnt[t * NN + j], 1);
}

// ---------------- scan: decoupled lookback -----------------------------------
__global__ void __launch_bounds__(1024) scan_kernel() {
    const int t   = blockIdx.y;
    const int ch  = blockIdx.x;
    const int tid = threadIdx.x;
    const int lane = tid & 31, w = tid >> 5;
    __shared__ int wsum[32];
    __shared__ int sh_prev, sh_total;

    int i = ch * 1024 + tid;
    int v = (i < NN) ? d_cnt[t * NN + i] : 0;

    int incl = v;
#pragma unroll
    for (int o = 1; o < 32; o <<= 1) {
        int u = __shfl_up_sync(0xffffffffu, incl, o);
        if (lane >= o) incl += u;
    }
    if (lane == 31) wsum[w] = incl;
    __syncthreads();
    if (w == 0) {
        int s = wsum[lane];
        int is = s;
#pragma unroll
        for (int o = 1; o < 32; o <<= 1) {
            int u = __shfl_up_sync(0xffffffffu, is, o);
            if (lane >= o) is += u;
        }
        wsum[lane] = is - s;
        if (lane == 31) sh_total = is;
    }
    __syncthreads();
    int blk_incl = wsum[w] + incl;

    if (tid == 0) {
        int prev = 0;
        if (ch > 0) {
            volatile int* vf = &d_sflag[t * SCH + ch - 1];
            int f;
            while ((f = *vf) == 0) { }
            __threadfence();
            prev = f - 1;
        }
        __threadfence();
        d_sflag[t * SCH + ch] = prev + sh_total + 1;
        sh_prev = prev;
    }
    __syncthreads();
    int prev = sh_prev;

    if (i < NN) {
        int excl = prev + blk_incl - v;
        d_off[t * (NN + 1) + i] = excl;
        d_cur[t * NN + i]       = excl;
    }
    if (ch == SCH - 1 && tid == 1023)
        d_off[t * (NN + 1) + NN] = prev + sh_total;
}

// ---------------- scatter edges into CSR -------------------------------------
__global__ void scatter_kernel(const int* __restrict__ ei, const float* __restrict__ ew) {
    int idx = blockIdx.x * 256 + threadIdx.x;
    if (idx >= TT * EE) return;
    int f = d_i64;
    int t = idx / EE, e = idx - t * EE;
    int i = ld_idx(ei, t * 2 * EE + e, f);
    int j = ld_idx(ei, t * 2 * EE + EE + e, f);
    int pos = atomicAdd(&d_cur[t * NN + j], 1);
    d_srcb[t * EE + pos] = i;
    d_eidb[t * EE + pos] = e;
    d_wb[t * EE + pos]   = ew[idx];
}

// ---------------- dedup (last edge index wins) + degrees ---------------------
__global__ void __launch_bounds__(256) dedup_kernel() {
    int gw   = (blockIdx.x * 256 + threadIdx.x) >> 5;
    int lane = threadIdx.x & 31;
    if (gw >= TT * NN) return;
    int t = gw / NN, j = gw - t * NN;
    int beg = d_off[t * (NN + 1) + j];
    int end = d_off[t * (NN + 1) + j + 1];

    float sum = 0.f;
    int selfw = 0;
    for (int p = beg + lane; p < end; p += 32) {
        int src = d_srcb[t * EE + p];
        int eid = d_eidb[t * EE + p];
        bool win = true;
        for (int q = beg; q < end; q++) {
            if (d_srcb[t * EE + q] == src && d_eidb[t * EE + q] > eid) { win = false; break; }
        }
        if (win) {
            sum += d_wb[t * EE + p];
            if (src == j) selfw = 1;
        } else {
            d_wb[t * EE + p] = 0.f;
        }
    }
#pragma unroll
    for (int o = 16; o; o >>= 1) {
        sum   += __shfl_xor_sync(0xffffffffu, sum, o);
        selfw |= __shfl_xor_sync(0xffffffffu, selfw, o);
    }
    if (lane == 0) {
        float diag = selfw ? 0.f : 1.f;
        d_diag[t * NN + j] = diag;
        d_dinv[t * NN + j] = rsqrtf(diag + sum);
    }
}

// ---------------- SpMM1 + ReLU + (h @ W2), p-loop unrolled x4 ----------------
__global__ void __launch_bounds__(256) spmm1_kernel(const float* __restrict__ b1,
                                                    const float* __restrict__ W2) {
    __shared__ float hs[8][HD];
    int gw   = (blockIdx.x * 256 + threadIdx.x) >> 5;
    int lane = threadIdx.x & 31;
    int wib  = (threadIdx.x >> 5);
    if (gw >= TT * NN) return;
    int t = gw / NN, j = gw - t * NN;
    const int tE = t * EE, tN = t * NN;
    int beg = d_off[t * (NN + 1) + j];
    int end = d_off[t * (NN + 1) + j + 1];

    float dj  = d_dinv[tN + j];
    float acc = d_diag[tN + j] * dj * d_h0[j * HD + lane];
    int p = beg;
    for (; p + 4 <= end; p += 4) {
        int s0 = d_srcb[tE + p],     s1 = d_srcb[tE + p + 1];
        int s2 = d_srcb[tE + p + 2], s3 = d_srcb[tE + p + 3];
        float c0 = d_wb[tE + p]     * d_dinv[tN + s0];
        float c1 = d_wb[tE + p + 1] * d_dinv[tN + s1];
        float c2 = d_wb[tE + p + 2] * d_dinv[tN + s2];
        float c3 = d_wb[tE + p + 3] * d_dinv[tN + s3];
        float v0 = d_h0[s0 * HD + lane], v1 = d_h0[s1 * HD + lane];
        float v2 = d_h0[s2 * HD + lane], v3 = d_h0[s3 * HD + lane];
        acc = fmaf(c0, v0, acc); acc = fmaf(c1, v1, acc);
        acc = fmaf(c2, v2, acc); acc = fmaf(c3, v3, acc);
    }
    for (; p < end; p++) {
        int s = d_srcb[tE + p];
        acc = fmaf(d_wb[tE + p] * d_dinv[tN + s], d_h0[s * HD + lane], acc);
    }
    float h = fmaxf(fmaf(acc, dj, b1[lane]), 0.f);
    hs[wib][lane] = h;
    __syncwarp();
    if (lane < ZD) {
        float s = 0.f;
#pragma unroll
        for (int c = 0; c < HD; c++) s = fmaf(hs[wib][c], W2[c * ZD + lane], s);
        d_g[(size_t)gw * ZD + lane] = s;
    }
}

// ---------------- SpMM2 + tanh (2 nodes/warp), p-loop unrolled x4 ------------
__global__ void __launch_bounds__(256) spmm2_kernel(const float* __restrict__ b2,
                                                    float* __restrict__ out) {
    int gwarp = (blockIdx.x * 256 + threadIdx.x) >> 5;
    int lane  = threadIdx.x & 31;
    int half  = lane >> 4, k = lane & 15;
    int node  = gwarp * 2 + half;
    if (node >= TT * NN) return;
    int t = node / NN, j = node - t * NN;
    const int tE = t * EE, tN = t * NN;
    int beg = d_off[t * (NN + 1) + j];
    int end = d_off[t * (NN + 1) + j + 1];

    float dj  = d_dinv[tN + j];
    float acc = d_diag[tN + j] * dj * d_g[(size_t)node * ZD + k];
    int p = beg;
    for (; p + 4 <= end; p += 4) {
        int s0 = d_srcb[tE + p],     s1 = d_srcb[tE + p + 1];
        int s2 = d_srcb[tE + p + 2], s3 = d_srcb[tE + p + 3];
        float c0 = d_wb[tE + p]     * d_dinv[tN + s0];
        float c1 = d_wb[tE + p + 1] * d_dinv[tN + s1];
        float c2 = d_wb[tE + p + 2] * d_dinv[tN + s2];
        float c3 = d_wb[tE + p + 3] * d_dinv[tN + s3];
        float v0 = d_g[(size_t)(tN + s0) * ZD + k], v1 = d_g[(size_t)(tN + s1) * ZD + k];
        float v2 = d_g[(size_t)(tN + s2) * ZD + k], v3 = d_g[(size_t)(tN + s3) * ZD + k];
        acc = fmaf(c0, v0, acc); acc = fmaf(c1, v1, acc);
        acc = fmaf(c2, v2, acc); acc = fmaf(c3, v3, acc);
    }
    for (; p < end; p++) {
        int s = d_srcb[tE + p];
        acc = fmaf(d_wb[tE + p] * d_dinv[tN + s], d_g[(size_t)(tN + s) * ZD + k], acc);
    }
    out[(size_t)node * ZD + k] = tanhf(fmaf(acc, dj, b2[k]));
}

// ---------------- launch (gemm = launch #6 for ncu) ---------------------------
extern "C" void kernel_launch(void* const* d_in, const int* in_sizes, int n_in,
                              void* d_out, int out_size) {
    const float* x  = (const float*)d_in[0];
    const int*   ei = (const int*)d_in[1];
    const float* ew = (const float*)d_in[2];
    const float* W1 = (const float*)d_in[3];
    const float* b1 = (const float*)d_in[4];
    const float* W2 = (const float*)d_in[5];
    const float* b2 = (const float*)d_in[6];
    float* out = (float*)d_out;

    cudaFuncSetAttribute(gemm_kernel, cudaFuncAttributeMaxDynamicSharedMemorySize, GEMM_SMEM);

    void *pcnt = nullptr, *pflag = nullptr, *ph0 = nullptr;
    cudaGetSymbolAddress(&pcnt, d_cnt);
    cudaGetSymbolAddress(&pflag, d_sflag);
    cudaGetSymbolAddress(&ph0, d_h0);
    cudaMemsetAsync(pcnt, 0, sizeof(int) * TT * NN);              // 1
    cudaMemsetAsync(pflag, 0, sizeof(int) * TT * SCH);            // 2
    cudaMemsetAsync(ph0, 0, sizeof(float) * NN * HD);             // 3

    detect_kernel<<<1, 32>>>(ei);                                 // 4
    hist_kernel<<<(TT * EE + 255) / 256, 256>>>(ei);              // 5
    gemm_kernel<<<dim3((NN + BMg - 1) / BMg, KSPLIT), 256, GEMM_SMEM>>>(x, W1);  // 6 (profiled)
    scan_kernel<<<dim3(SCH, TT), 1024>>>();                       // 7
    scatter_kernel<<<(TT * EE + 255) / 256, 256>>>(ei, ew);       // 8
    dedup_kernel<<<(TT * NN * 32 + 255) / 256, 256>>>();          // 9
    spmm1_kernel<<<(TT * NN * 32 + 255) / 256, 256>>>(b1, W2);    // 10
    spmm2_kernel<<<(TT * NN * 16 + 255) / 256, 256>>>(b2, out);   // 11
}

// round 5
// speedup vs baseline: 1.7893x; 1.0672x over previous
#include <cuda_runtime.h>
#include <cstdint>
#include <math.h>

#define NN 8746
#define KD 8746
#define HD 32
#define ZD 16
#define TT 6
#define EE 100000

// GEMM tiling: BM=128, BK=32, split-K x4 (grid 276 = single wave), 4-stage pipe
#define BMg 128
#define BKg 32
#define STg 4
#define KSPLIT 4
#define TPC 69                         // tiles per K-chunk (last chunk: 67)
#define NTILE_TOT 274                  // ceil(8746/32)
#define XSTR 36                        // x row stride in floats
#define WSTR 40                        // W row stride in floats
#define XTILE_BYTES (BMg * XSTR * 4)   // 18432
#define WTILE_BYTES (BKg * WSTR * 4)   // 5120
#define GEMM_SMEM (STg * (XTILE_BYTES + WTILE_BYTES))   // 94208

#define SCH 9                          // scan chunks per timestep

// ---------------- scratch (device globals; no allocations allowed) ----------
__device__ float d_h0[NN * HD];
__device__ int   d_cnt[TT * NN];
__device__ int   d_off[TT * (NN + 1)];
__device__ int   d_cur[TT * NN];
__device__ int   d_srcb[TT * EE];
__device__ int   d_eidb[TT * EE];
__device__ float d_wb[TT * EE];
__device__ float d_diag[TT * NN];
__device__ float d_dinv[TT * NN];
__device__ float d_g[TT * NN * ZD];
__device__ int   d_i64;

// ---------------- helpers ---------------------------------------------------
__device__ __forceinline__ void cp16(uint32_t dst, const void* src, int nb) {
    asm volatile("cp.async.cg.shared.global [%0], [%1], 16, %2;\n"
                 :: "r"(dst), "l"(src), "r"(nb) : "memory");
}
__device__ __forceinline__ uint32_t f2tf(float f) {
    uint32_t r;
    asm("cvt.rna.tf32.f32 %0, %1;" : "=r"(r) : "f"(f));
    return r;
}
__device__ __forceinline__ int ld_idx(const int* ei, int pos, int f) {
    return f ? ei[2 * pos] : ei[pos];
}

// ---------------- dtype detect ----------------------------------------------
__global__ void detect_kernel(const int* __restrict__ ei) {
    if (threadIdx.x == 0 && blockIdx.x == 0) {
        d_i64 = (ei[1] == 0 && ei[3] == 0 && ei[5] == 0 && ei[7] == 0 && ei[9] == 0) ? 1 : 0;
    }
}

// ---------------- GEMM: h0 += x @ W1 (tf32 mma, warp-coalesced cp.async) -----
// x-copy mapping: warp w owns rows [16w, 16w+16) = 8 row-pairs. Each pair needs
// 17 16B chunks (even row: 8 aligned chunks; odd row: 9 chunks, window shifted
// -8B for 16B alignment). chunk q = i*32+lane walks pairs in order, so
// consecutive lanes cover contiguous bytes (128B/144B runs -> coalesced lines).
__global__ void __launch_bounds__(256, 2)
gemm_kernel(const float* __restrict__ x, const float* __restrict__ W1) {
    extern __shared__ __align__(16) char smem[];
    float* xs = (float*)smem;                              // [STg][BMg*XSTR]
    float* ws = (float*)(smem + STg * XTILE_BYTES);        // [STg][BKg*WSTR]

    const int tid  = threadIdx.x;
    const int lane = tid & 31;
    const int warp = tid >> 5;
    const int m0   = blockIdx.x * BMg;
    const int tile0 = blockIdx.y * TPC;
    const int ntile = min(TPC, NTILE_TOT - tile0);
    const int kbeg  = tile0 * BKg;
    const bool clampblk = (m0 + BMg > NN);
    const long XEND = (long)NN * KD;

    const uint32_t xs_u = (uint32_t)__cvta_generic_to_shared(xs);
    const uint32_t ws_u = (uint32_t)__cvta_generic_to_shared(ws);

    // precompute this thread's 5 copy slots (136 chunks per warp)
    long     xoff[5];
    uint32_t xdst[5];
    int      xok[5];
#pragma unroll
    for (int i = 0; i < 5; i++) {
        int q = i * 32 + lane;
        xok[i] = 0;
        if (q < 136) {
            int pair = q / 17, k = q - pair * 17;
            int odd  = (k >= 8) ? 1 : 0;
            int row  = warp * 16 + pair * 2 + odd;
            int cc   = odd ? (k - 8) : k;
            if (!(clampblk && row >= NN - m0)) {
                xoff[i] = (long)(m0 + row) * KD + kbeg + cc * 4 - (odd ? 2 : 0);
                xdst[i] = (uint32_t)(row * XSTR + cc * 4) * 4;
                xok[i]  = 1;
            }
        }
    }
    // W copy: 32 k-rows x 128B, lanes 0-7 cover one row contiguously
    const int wkk = tid >> 3, wg = tid & 7;
    const uint32_t wdst = (uint32_t)(wkk * WSTR + wg * 4) * 4;

    auto load_tiles = [&](int buf, int tileIdx) {
        const uint32_t xb = xs_u + (uint32_t)buf * XTILE_BYTES;
#pragma unroll
        for (int i = 0; i < 5; i++) {
            if (xok[i]) {
                long o = xoff[i] + (long)tileIdx * BKg;
                int nb = 16;
                if (clampblk) {
                    long remB = (XEND - o) * 4;
                    if (remB < 16) { nb = remB > 0 ? (int)remB : 0; if (nb == 0) o = 0; }
                }
                cp16(xb + xdst[i], x + o, nb);
            }
        }
        {
            int gk = kbeg + tileIdx * BKg + wkk;
            int nb = (gk < KD) ? 16 : 0;
            int ga = (gk < KD) ? gk : 0;
            cp16(ws_u + (uint32_t)buf * WTILE_BYTES + wdst,
                 W1 + (long)ga * HD + wg * 4, nb);
        }
    };

    // prologue: 3 stages
#pragma unroll
    for (int s = 0; s < STg - 1; s++) {
        load_tiles(s, s);
        asm volatile("cp.async.commit_group;\n" ::: "memory");
    }

    float acc[4][4];
#pragma unroll
    for (int a = 0; a < 4; a++)
#pragma unroll
        for (int b = 0; b < 4; b++) acc[a][b] = 0.f;

    const int arow = warp * 16 + (lane >> 2);
    const int sh   = (arow & 1) ? 2 : 0;       // odd rows stored shifted by 2 floats
    const int kq   = lane & 3;
    const int qn   = lane >> 2;

    for (int it = 0; it < ntile; it++) {
        asm volatile("cp.async.wait_group %0;\n" :: "n"(STg - 2) : "memory");
        __syncthreads();

        if (it + STg - 1 < ntile)
            load_tiles((it + STg - 1) & 3, it + STg - 1);
        asm volatile("cp.async.commit_group;\n" ::: "memory");

        const float* xb = xs + (it & 3) * (BMg * XSTR);
        const float* wb = ws + (it & 3) * (BKg * WSTR);
#pragma unroll
        for (int s = 0; s < 4; s++) {
            const int k8 = s * 8;
            uint32_t a0 = f2tf(xb[arow * XSTR + sh + k8 + kq]);
            uint32_t a1 = f2tf(xb[(arow + 8) * XSTR + sh + k8 + kq]);
            uint32_t a2 = f2tf(xb[arow * XSTR + sh + k8 + 4 + kq]);
            uint32_t a3 = f2tf(xb[(arow + 8) * XSTR + sh + k8 + 4 + kq]);
#pragma unroll
            for (int nt = 0; nt < 4; nt++) {
                uint32_t b0 = f2tf(wb[(k8 + kq) * WSTR + nt * 8 + qn]);
                uint32_t b1 = f2tf(wb[(k8 + 4 + kq) * WSTR + nt * 8 + qn]);
                asm volatile(
                    "mma.sync.aligned.m16n8k8.row.col.f32.tf32.tf32.f32 "
                    "{%0,%1,%2,%3}, {%4,%5,%6,%7}, {%8,%9}, {%0,%1,%2,%3};\n"
                    : "+f"(acc[nt][0]), "+f"(acc[nt][1]), "+f"(acc[nt][2]), "+f"(acc[nt][3])
                    : "r"(a0), "r"(a1), "r"(a2), "r"(a3), "r"(b0), "r"(b1));
            }
        }
    }

    // split-K epilogue: atomic accumulate
    const int r0 = m0 + arow;
    const int r1 = r0 + 8;
    const int c0 = (lane & 3) * 2;
#pragma unroll
    for (int nt = 0; nt < 4; nt++) {
        int c = nt * 8 + c0;
        if (r0 < NN) {
            atomicAdd(&d_h0[r0 * HD + c],     acc[nt][0]);
            atomicAdd(&d_h0[r0 * HD + c + 1], acc[nt][1]);
        }
        if (r1 < NN) {
            atomicAdd(&d_h0[r1 * HD + c],     acc[nt][2]);
            atomicAdd(&d_h0[r1 * HD + c + 1], acc[nt][3]);
        }
    }
}

// ---------------- edge histogram --------------------------------------------
__global__ void hist_kernel(const int* __restrict__ ei) {
    int idx = blockIdx.x * 256 + threadIdx.x;
    if (idx >= TT * EE) return;
    int f = d_i64;
    int t = idx / EE, e = idx - t * EE;
    int j = ld_idx(ei, t * 2 * EE + EE + e, f);
    atomicAdd(&d_cnt[t * NN + j], 1);
}

// ---------------- scan: redundant prefix (no cross-block chain) --------------
__global__ void __launch_bounds__(1024) scan_kernel() {
    const int t   = blockIdx.y;
    const int ch  = blockIdx.x;
    const int tid = threadIdx.x;
    const int lane = tid & 31, w = tid >> 5;
    __shared__ int wsum[32];
    __shared__ int psum[32];

    // sum of all chunks before ch (each thread strided, coalesced)
    int pre = 0;
    for (int i = tid; i < ch * 1024; i += 1024) pre += d_cnt[t * NN + i];

    int i = ch * 1024 + tid;
    int v = (i < NN) ? d_cnt[t * NN + i] : 0;

    // warp reductions/scans
    int incl = v;
#pragma unroll
    for (int o = 1; o < 32; o <<= 1) {
        int u = __shfl_up_sync(0xffffffffu, incl, o);
        if (lane >= o) incl += u;
    }
#pragma unroll
    for (int o = 16; o; o >>= 1) pre += __shfl_xor_sync(0xffffffffu, pre, o);

    if (lane == 31) wsum[w] = incl;
    if (lane == 0)  psum[w] = pre;
    __syncthreads();
    if (w == 0) {
        int s = wsum[lane];
        int is = s;
#pragma unroll
        for (int o = 1; o < 32; o <<= 1) {
            int u = __shfl_up_sync(0xffffffffu, is, o);
            if (lane >= o) is += u;
        }
        wsum[lane] = is - s;              // exclusive warp offsets
        int p = psum[lane];
#pragma unroll
        for (int o = 16; o; o >>= 1) p += __shfl_xor_sync(0xffffffffu, p, o);
        psum[lane] = p;                   // total of prior chunks (same in all lanes)
    }
    __syncthreads();

    int prev = psum[0];
    int blk_incl = wsum[w] + incl;

    if (i < NN) {
        int excl = prev + blk_incl - v;
        d_off[t * (NN + 1) + i] = excl;
        d_cur[t * NN + i]       = excl;
    }
    if (ch == SCH - 1 && tid == 1023)
        d_off[t * (NN + 1) + NN] = prev + blk_incl;
}

// ---------------- scatter edges into CSR -------------------------------------
__global__ void scatter_kernel(const int* __restrict__ ei, const float* __restrict__ ew) {
    int idx = blockIdx.x * 256 + threadIdx.x;
    if (idx >= TT * EE) return;
    int f = d_i64;
    int t = idx / EE, e = idx - t * EE;
    int i = ld_idx(ei, t * 2 * EE + e, f);
    int j = ld_idx(ei, t * 2 * EE + EE + e, f);
    int pos = atomicAdd(&d_cur[t * NN + j], 1);
    d_srcb[t * EE + pos] = i;
    d_eidb[t * EE + pos] = e;
    d_wb[t * EE + pos]   = ew[idx];
}

// ---------------- dedup (last edge index wins) + degrees ---------------------
__global__ void __launch_bounds__(256) dedup_kernel() {
    int gw   = (blockIdx.x * 256 + threadIdx.x) >> 5;
    int lane = threadIdx.x & 31;
    if (gw >= TT * NN) return;
    int t = gw / NN, j = gw - t * NN;
    int beg = d_off[t * (NN + 1) + j];
    int end = d_off[t * (NN + 1) + j + 1];

    float sum = 0.f;
    int selfw = 0;
    for (int p = beg + lane; p < end; p += 32) {
        int src = d_srcb[t * EE + p];
        int eid = d_eidb[t * EE + p];
        bool win = true;
        for (int q = beg; q < end; q++) {
            if (d_srcb[t * EE + q] == src && d_eidb[t * EE + q] > eid) { win = false; break; }
        }
        if (win) {
            sum += d_wb[t * EE + p];
            if (src == j) selfw = 1;
        } else {
            d_wb[t * EE + p] = 0.f;
        }
    }
#pragma unroll
    for (int o = 16; o; o >>= 1) {
        sum   += __shfl_xor_sync(0xffffffffu, sum, o);
        selfw |= __shfl_xor_sync(0xffffffffu, selfw, o);
    }
    if (lane == 0) {
        float diag = selfw ? 0.f : 1.f;
        d_diag[t * NN + j] = diag;
        d_dinv[t * NN + j] = rsqrtf(diag + sum);
    }
}

// ---------------- SpMM1 + ReLU + (h @ W2), p-loop unrolled x4 ----------------
__global__ void __launch_bounds__(256) spmm1_kernel(const float* __restrict__ b1,
                                                    const float* __restrict__ W2) {
    __shared__ float hs[8][HD];
    int gw   = (blockIdx.x * 256 + threadIdx.x) >> 5;
    int lane = threadIdx.x & 31;
    int wib  = (threadIdx.x >> 5);
    if (gw >= TT * NN) return;
    int t = gw / NN, j = gw - t * NN;
    const int tE = t * EE, tN = t * NN;
    int beg = d_off[t * (NN + 1) + j];
    int end = d_off[t * (NN + 1) + j + 1];

    float dj  = d_dinv[tN + j];
    float acc = d_diag[tN + j] * dj * d_h0[j * HD + lane];
    int p = beg;
    for (; p + 4 <= end; p += 4) {
        int s0 = d_srcb[tE + p],     s1 = d_srcb[tE + p + 1];
        int s2 = d_srcb[tE + p + 2], s3 = d_srcb[tE + p + 3];
        float c0 = d_wb[tE + p]     * d_dinv[tN + s0];
        float c1 = d_wb[tE + p + 1] * d_dinv[tN + s1];
        float c2 = d_wb[tE + p + 2] * d_dinv[tN + s2];
        float c3 = d_wb[tE + p + 3] * d_dinv[tN + s3];
        float v0 = d_h0[s0 * HD + lane], v1 = d_h0[s1 * HD + lane];
        float v2 = d_h0[s2 * HD + lane], v3 = d_h0[s3 * HD + lane];
        acc = fmaf(c0, v0, acc); acc = fmaf(c1, v1, acc);
        acc = fmaf(c2, v2, acc); acc = fmaf(c3, v3, acc);
    }
    for (; p < end; p++) {
        int s = d_srcb[tE + p];
        acc = fmaf(d_wb[tE + p] * d_dinv[tN + s], d_h0[s * HD + lane], acc);
    }
    float h = fmaxf(fmaf(acc, dj, b1[lane]), 0.f);
    hs[wib][lane] = h;
    __syncwarp();
    if (lane < ZD) {
        float s = 0.f;
#pragma unroll
        for (int c = 0; c < HD; c++) s = fmaf(hs[wib][c], W2[c * ZD + lane], s);
        d_g[(size_t)gw * ZD + lane] = s;
    }
}

// ---------------- SpMM2 + tanh (2 nodes/warp), p-loop unrolled x4 ------------
__global__ void __launch_bounds__(256) spmm2_kernel(const float* __restrict__ b2,
                                                    float* __restrict__ out) {
    int gwarp = (blockIdx.x * 256 + threadIdx.x) >> 5;
    int lane  = threadIdx.x & 31;
    int half  = lane >> 4, k = lane & 15;
    int node  = gwarp * 2 + half;
    if (node >= TT * NN) return;
    int t = node / NN, j = node - t * NN;
    const int tE = t * EE, tN = t * NN;
    int beg = d_off[t * (NN + 1) + j];
    int end = d_off[t * (NN + 1) + j + 1];

    float dj  = d_dinv[tN + j];
    float acc = d_diag[tN + j] * dj * d_g[(size_t)node * ZD + k];
    int p = beg;
    for (; p + 4 <= end; p += 4) {
        int s0 = d_srcb[tE + p],     s1 = d_srcb[tE + p + 1];
        int s2 = d_srcb[tE + p + 2], s3 = d_srcb[tE + p + 3];
        float c0 = d_wb[tE + p]     * d_dinv[tN + s0];
        float c1 = d_wb[tE + p + 1] * d_dinv[tN + s1];
        float c2 = d_wb[tE + p + 2] * d_dinv[tN + s2];
        float c3 = d_wb[tE + p + 3] * d_dinv[tN + s3];
        float v0 = d_g[(size_t)(tN + s0) * ZD + k], v1 = d_g[(size_t)(tN + s1) * ZD + k];
        float v2 = d_g[(size_t)(tN + s2) * ZD + k], v3 = d_g[(size_t)(tN + s3) * ZD + k];
        acc = fmaf(c0, v0, acc); acc = fmaf(c1, v1, acc);
        acc = fmaf(c2, v2, acc); acc = fmaf(c3, v3, acc);
    }
    for (; p < end; p++) {
        int s = d_srcb[tE + p];
        acc = fmaf(d_wb[tE + p] * d_dinv[tN + s], d_g[(size_t)(tN + s) * ZD + k], acc);
    }
    out[(size_t)node * ZD + k] = tanhf(fmaf(acc, dj, b2[k]));
}

// ---------------- launch (2 memsets; gemm = slot 6 as verified in R3) --------
extern "C" void kernel_launch(void* const* d_in, const int* in_sizes, int n_in,
                              void* d_out, int out_size) {
    const float* x  = (const float*)d_in[0];
    const int*   ei = (const int*)d_in[1];
    const float* ew = (const float*)d_in[2];
    const float* W1 = (const float*)d_in[3];
    const float* b1 = (const float*)d_in[4];
    const float* W2 = (const float*)d_in[5];
    const float* b2 = (const float*)d_in[6];
    float* out = (float*)d_out;

    cudaFuncSetAttribute(gemm_kernel, cudaFuncAttributeMaxDynamicSharedMemorySize, GEMM_SMEM);

    void *pcnt = nullptr, *ph0 = nullptr;
    cudaGetSymbolAddress(&pcnt, d_cnt);
    cudaGetSymbolAddress(&ph0, d_h0);
    cudaMemsetAsync(ph0, 0, sizeof(float) * NN * HD);             // 1
    cudaMemsetAsync(pcnt, 0, sizeof(int) * TT * NN);              // 2

    detect_kernel<<<1, 32>>>(ei);                                 // 3
    hist_kernel<<<(TT * EE + 255) / 256, 256>>>(ei);              // 4
    scan_kernel<<<dim3(SCH, TT), 1024>>>();                       // 5
    gemm_kernel<<<dim3((NN + BMg - 1) / BMg, KSPLIT), 256, GEMM_SMEM>>>(x, W1);  // 6 (profiled)
    scatter_kernel<<<(TT * EE + 255) / 256, 256>>>(ei, ew);       // 7
    dedup_kernel<<<(TT * NN * 32 + 255) / 256, 256>>>();          // 8
    spmm1_kernel<<<(TT * NN * 32 + 255) / 256, 256>>>(b1, W2);    // 9
    spmm2_kernel<<<(TT * NN * 16 + 255) / 256, 256>>>(b2, out);   // 10
}

// round 6
// speedup vs baseline: 1.8058x; 1.0092x over previous
#include <cuda_runtime.h>
#include <cstdint>
#include <math.h>

#define NN 8746
#define KD 8746
#define HD 32
#define ZD 16
#define TT 6
#define EE 100000

// GEMM tiling: BM=128, BK=32, split-K x4 (grid 276 = single wave), 4-stage pipe
#define BMg 128
#define BKg 32
#define STg 4
#define KSPLIT 4
#define TPC 69                         // tiles per K-chunk (last chunk: 67)
#define NTILE_TOT 274                  // ceil(8746/32)
#define XSTR 36                        // x row stride in floats
#define WSTR 40                        // W row stride in floats
#define XTILE_BYTES (BMg * XSTR * 4)   // 18432
#define WTILE_BYTES (BKg * WSTR * 4)   // 5120
#define GEMM_SMEM (STg * (XTILE_BYTES + WTILE_BYTES))   // 94208

#define SCH 9                          // scan chunks per timestep

// ---------------- scratch (device globals; no allocations allowed) ----------
__device__ float d_h0[NN * HD];
__device__ int   d_cnt[TT * NN];
__device__ int   d_off[TT * (NN + 1)];
__device__ int   d_cur[TT * NN];
__device__ int   d_srcb[TT * EE];
__device__ int   d_eidb[TT * EE];
__device__ float d_wb[TT * EE];
__device__ float d_diag[TT * NN];
__device__ float d_dinv[TT * NN];
__device__ float d_g[TT * NN * ZD];
__device__ int   d_i64;

// ---------------- helpers ---------------------------------------------------
__device__ __forceinline__ void cp16(uint32_t dst, const void* src, int nb) {
    asm volatile("cp.async.cg.shared.global [%0], [%1], 16, %2;\n"
                 :: "r"(dst), "l"(src), "r"(nb) : "memory");
}
__device__ __forceinline__ uint32_t f2tf(float f) {
    uint32_t r;
    asm("cvt.rna.tf32.f32 %0, %1;" : "=r"(r) : "f"(f));
    return r;
}
__device__ __forceinline__ int ld_idx(const int* ei, int pos, int f) {
    return f ? ei[2 * pos] : ei[pos];
}

// ---------------- dtype detect ----------------------------------------------
__global__ void detect_kernel(const int* __restrict__ ei) {
    if (threadIdx.x == 0 && blockIdx.x == 0) {
        d_i64 = (ei[1] == 0 && ei[3] == 0 && ei[5] == 0 && ei[7] == 0 && ei[9] == 0) ? 1 : 0;
    }
}

// ---------------- GEMM: h0 += x @ W1 (tf32 mma, warp-coalesced cp.async) -----
// x-copy mapping: warp w owns rows [16w, 16w+16) = 8 row-pairs. Each pair needs
// 17 16B chunks (even row: 8 aligned chunks; odd row: 9 chunks, window shifted
// -8B for 16B alignment). chunk q = i*32+lane walks pairs in order, so
// consecutive lanes cover contiguous bytes (128B/144B runs -> coalesced lines).
__global__ void __launch_bounds__(256, 2)
gemm_kernel(const float* __restrict__ x, const float* __restrict__ W1) {
    extern __shared__ __align__(16) char smem[];
    float* xs = (float*)smem;                              // [STg][BMg*XSTR]
    float* ws = (float*)(smem + STg * XTILE_BYTES);        // [STg][BKg*WSTR]

    const int tid  = threadIdx.x;
    const int lane = tid & 31;
    const int warp = tid >> 5;
    const int m0   = blockIdx.x * BMg;
    const int tile0 = blockIdx.y * TPC;
    const int ntile = min(TPC, NTILE_TOT - tile0);
    const int kbeg  = tile0 * BKg;
    const bool clampblk = (m0 + BMg > NN);
    const long XEND = (long)NN * KD;

    const uint32_t xs_u = (uint32_t)__cvta_generic_to_shared(xs);
    const uint32_t ws_u = (uint32_t)__cvta_generic_to_shared(ws);

    // precompute this thread's 5 copy slots (136 chunks per warp)
    long     xoff[5];
    uint32_t xdst[5];
    int      xok[5];
#pragma unroll
    for (int i = 0; i < 5; i++) {
        int q = i * 32 + lane;
        xok[i] = 0;
        if (q < 136) {
            int pair = q / 17, k = q - pair * 17;
            int odd  = (k >= 8) ? 1 : 0;
            int row  = warp * 16 + pair * 2 + odd;
            int cc   = odd ? (k - 8) : k;
            if (!(clampblk && row >= NN - m0)) {
                xoff[i] = (long)(m0 + row) * KD + kbeg + cc * 4 - (odd ? 2 : 0);
                xdst[i] = (uint32_t)(row * XSTR + cc * 4) * 4;
                xok[i]  = 1;
            }
        }
    }
    // W copy: 32 k-rows x 128B, lanes 0-7 cover one row contiguously
    const int wkk = tid >> 3, wg = tid & 7;
    const uint32_t wdst = (uint32_t)(wkk * WSTR + wg * 4) * 4;

    auto load_tiles = [&](int buf, int tileIdx) {
        const uint32_t xb = xs_u + (uint32_t)buf * XTILE_BYTES;
#pragma unroll
        for (int i = 0; i < 5; i++) {
            if (xok[i]) {
                long o = xoff[i] + (long)tileIdx * BKg;
                int nb = 16;
                if (clampblk) {
                    long remB = (XEND - o) * 4;
                    if (remB < 16) { nb = remB > 0 ? (int)remB : 0; if (nb == 0) o = 0; }
                }
                cp16(xb + xdst[i], x + o, nb);
            }
        }
        {
            int gk = kbeg + tileIdx * BKg + wkk;
            int nb = (gk < KD) ? 16 : 0;
            int ga = (gk < KD) ? gk : 0;
            cp16(ws_u + (uint32_t)buf * WTILE_BYTES + wdst,
                 W1 + (long)ga * HD + wg * 4, nb);
        }
    };

    // prologue: 3 stages
#pragma unroll
    for (int s = 0; s < STg - 1; s++) {
        load_tiles(s, s);
        asm volatile("cp.async.commit_group;\n" ::: "memory");
    }

    float acc[4][4];
#pragma unroll
    for (int a = 0; a < 4; a++)
#pragma unroll
        for (int b = 0; b < 4; b++) acc[a][b] = 0.f;

    const int arow = warp * 16 + (lane >> 2);
    const int sh   = (arow & 1) ? 2 : 0;       // odd rows stored shifted by 2 floats
    const int kq   = lane & 3;
    const int qn   = lane >> 2;

    for (int it = 0; it < ntile; it++) {
        asm volatile("cp.async.wait_group %0;\n" :: "n"(STg - 2) : "memory");
        __syncthreads();

        if (it + STg - 1 < ntile)
            load_tiles((it + STg - 1) & 3, it + STg - 1);
        asm volatile("cp.async.commit_group;\n" ::: "memory");

        const float* xb = xs + (it & 3) * (BMg * XSTR);
        const float* wb = ws + (it & 3) * (BKg * WSTR);
#pragma unroll
        for (int s = 0; s < 4; s++) {
            const int k8 = s * 8;
            uint32_t a0 = f2tf(xb[arow * XSTR + sh + k8 + kq]);
            uint32_t a1 = f2tf(xb[(arow + 8) * XSTR + sh + k8 + kq]);
            uint32_t a2 = f2tf(xb[arow * XSTR + sh + k8 + 4 + kq]);
            uint32_t a3 = f2tf(xb[(arow + 8) * XSTR + sh + k8 + 4 + kq]);
#pragma unroll
            for (int nt = 0; nt < 4; nt++) {
                uint32_t b0 = f2tf(wb[(k8 + kq) * WSTR + nt * 8 + qn]);
                uint32_t b1 = f2tf(wb[(k8 + 4 + kq) * WSTR + nt * 8 + qn]);
                asm volatile(
                    "mma.sync.aligned.m16n8k8.row.col.f32.tf32.tf32.f32 "
                    "{%0,%1,%2,%3}, {%4,%5,%6,%7}, {%8,%9}, {%0,%1,%2,%3};\n"
                    : "+f"(acc[nt][0]), "+f"(acc[nt][1]), "+f"(acc[nt][2]), "+f"(acc[nt][3])
                    : "r"(a0), "r"(a1), "r"(a2), "r"(a3), "r"(b0), "r"(b1));
            }
        }
    }

    // split-K epilogue: atomic accumulate
    const int r0 = m0 + arow;
    const int r1 = r0 + 8;
    const int c0 = (lane & 3) * 2;
#pragma unroll
    for (int nt = 0; nt < 4; nt++) {
        int c = nt * 8 + c0;
        if (r0 < NN) {
            atomicAdd(&d_h0[r0 * HD + c],     acc[nt][0]);
            atomicAdd(&d_h0[r0 * HD + c + 1], acc[nt][1]);
        }
        if (r1 < NN) {
            atomicAdd(&d_h0[r1 * HD + c],     acc[nt][2]);
            atomicAdd(&d_h0[r1 * HD + c + 1], acc[nt][3]);
        }
    }
}

// ---------------- edge histogram --------------------------------------------
__global__ void hist_kernel(const int* __restrict__ ei) {
    int idx = blockIdx.x * 256 + threadIdx.x;
    if (idx >= TT * EE) return;
    int f = d_i64;
    int t = idx / EE, e = idx - t * EE;
    int j = ld_idx(ei, t * 2 * EE + EE + e, f);
    atomicAdd(&d_cnt[t * NN + j], 1);
}

// ---------------- scan: redundant prefix (no cross-block chain) --------------
__global__ void __launch_bounds__(1024) scan_kernel() {
    const int t   = blockIdx.y;
    const int ch  = blockIdx.x;
    const int tid = threadIdx.x;
    const int lane = tid & 31, w = tid >> 5;
    __shared__ int wsum[32];
    __shared__ int psum[32];

    // sum of all chunks before ch (each thread strided, coalesced)
    int pre = 0;
    for (int i = tid; i < ch * 1024; i += 1024) pre += d_cnt[t * NN + i];

    int i = ch * 1024 + tid;
    int v = (i < NN) ? d_cnt[t * NN + i] : 0;

    // warp reductions/scans
    int incl = v;
#pragma unroll
    for (int o = 1; o < 32; o <<= 1) {
        int u = __shfl_up_sync(0xffffffffu, incl, o);
        if (lane >= o) incl += u;
    }
#pragma unroll
    for (int o = 16; o; o >>= 1) pre += __shfl_xor_sync(0xffffffffu, pre, o);

    if (lane == 31) wsum[w] = incl;
    if (lane == 0)  psum[w] = pre;
    __syncthreads();
    if (w == 0) {
        int s = wsum[lane];
        int is = s;
#pragma unroll
        for (int o = 1; o < 32; o <<= 1) {
            int u = __shfl_up_sync(0xffffffffu, is, o);
            if (lane >= o) is += u;
        }
        wsum[lane] = is - s;              // exclusive warp offsets
        int p = psum[lane];
#pragma unroll
        for (int o = 16; o; o >>= 1) p += __shfl_xor_sync(0xffffffffu, p, o);
        psum[lane] = p;                   // total of prior chunks (same in all lanes)
    }
    __syncthreads();

    int prev = psum[0];
    int blk_incl = wsum[w] + incl;

    if (i < NN) {
        int excl = prev + blk_incl - v;
        d_off[t * (NN + 1) + i] = excl;
        d_cur[t * NN + i]       = excl;
    }
    if (ch == SCH - 1 && tid == 1023)
        d_off[t * (NN + 1) + NN] = prev + blk_incl;
}

// ---------------- scatter edges into CSR -------------------------------------
__global__ void scatter_kernel(const int* __restrict__ ei, const float* __restrict__ ew) {
    int idx = blockIdx.x * 256 + threadIdx.x;
    if (idx >= TT * EE) return;
    int f = d_i64;
    int t = idx / EE, e = idx - t * EE;
    int i = ld_idx(ei, t * 2 * EE + e, f);
    int j = ld_idx(ei, t * 2 * EE + EE + e, f);
    int pos = atomicAdd(&d_cur[t * NN + j], 1);
    d_srcb[t * EE + pos] = i;
    d_eidb[t * EE + pos] = e;
    d_wb[t * EE + pos]   = ew[idx];
}

// ---------------- dedup (last edge index wins) + degrees ---------------------
__global__ void __launch_bounds__(256) dedup_kernel() {
    int gw   = (blockIdx.x * 256 + threadIdx.x) >> 5;
    int lane = threadIdx.x & 31;
    if (gw >= TT * NN) return;
    int t = gw / NN, j = gw - t * NN;
    int beg = d_off[t * (NN + 1) + j];
    int end = d_off[t * (NN + 1) + j + 1];

    float sum = 0.f;
    int selfw = 0;
    for (int p = beg + lane; p < end; p += 32) {
        int src = d_srcb[t * EE + p];
        int eid = d_eidb[t * EE + p];
        bool win = true;
        for (int q = beg; q < end; q++) {
            if (d_srcb[t * EE + q] == src && d_eidb[t * EE + q] > eid) { win = false; break; }
        }
        if (win) {
            sum += d_wb[t * EE + p];
            if (src == j) selfw = 1;
        } else {
            d_wb[t * EE + p] = 0.f;
        }
    }
#pragma unroll
    for (int o = 16; o; o >>= 1) {
        sum   += __shfl_xor_sync(0xffffffffu, sum, o);
        selfw |= __shfl_xor_sync(0xffffffffu, selfw, o);
    }
    if (lane == 0) {
        float diag = selfw ? 0.f : 1.f;
        d_diag[t * NN + j] = diag;
        d_dinv[t * NN + j] = rsqrtf(diag + sum);
    }
}

// ---------------- SpMM1 + ReLU + (h @ W2), p-loop unrolled x4 ----------------
__global__ void __launch_bounds__(256) spmm1_kernel(const float* __restrict__ b1,
                                                    const float* __restrict__ W2) {
    __shared__ float hs[8][HD];
    int gw   = (blockIdx.x * 256 + threadIdx.x) >> 5;
    int lane = threadIdx.x & 31;
    int wib  = (threadIdx.x >> 5);
    if (gw >= TT * NN) return;
    int t = gw / NN, j = gw - t * NN;
    const int tE = t * EE, tN = t * NN;
    int beg = d_off[t * (NN + 1) + j];
    int end = d_off[t * (NN + 1) + j + 1];

    float dj  = d_dinv[tN + j];
    float acc = d_diag[tN + j] * dj * d_h0[j * HD + lane];
    int p = beg;
    for (; p + 4 <= end; p += 4) {
        int s0 = d_srcb[tE + p],     s1 = d_srcb[tE + p + 1];
        int s2 = d_srcb[tE + p + 2], s3 = d_srcb[tE + p + 3];
        float c0 = d_wb[tE + p]     * d_dinv[tN + s0];
        float c1 = d_wb[tE + p + 1] * d_dinv[tN + s1];
        float c2 = d_wb[tE + p + 2] * d_dinv[tN + s2];
        float c3 = d_wb[tE + p + 3] * d_dinv[tN + s3];
        float v0 = d_h0[s0 * HD + lane], v1 = d_h0[s1 * HD + lane];
        float v2 = d_h0[s2 * HD + lane], v3 = d_h0[s3 * HD + lane];
        acc = fmaf(c0, v0, acc); acc = fmaf(c1, v1, acc);
        acc = fmaf(c2, v2, acc); acc = fmaf(c3, v3, acc);
    }
    for (; p < end; p++) {
        int s = d_srcb[tE + p];
        acc = fmaf(d_wb[tE + p] * d_dinv[tN + s], d_h0[s * HD + lane], acc);
    }
    float h = fmaxf(fmaf(acc, dj, b1[lane]), 0.f);
    hs[wib][lane] = h;
    __syncwarp();
    if (lane < ZD) {
        float s = 0.f;
#pragma unroll
        for (int c = 0; c < HD; c++) s = fmaf(hs[wib][c], W2[c * ZD + lane], s);
        d_g[(size_t)gw * ZD + lane] = s;
    }
}

// ---------------- SpMM2 + tanh (2 nodes/warp), p-loop unrolled x4 ------------
__global__ void __launch_bounds__(256) spmm2_kernel(const float* __restrict__ b2,
                                                    float* __restrict__ out) {
    int gwarp = (blockIdx.x * 256 + threadIdx.x) >> 5;
    int lane  = threadIdx.x & 31;
    int half  = lane >> 4, k = lane & 15;
    int node  = gwarp * 2 + half;
    if (node >= TT * NN) return;
    int t = node / NN, j = node - t * NN;
    const int tE = t * EE, tN = t * NN;
    int beg = d_off[t * (NN + 1) + j];
    int end = d_off[t * (NN + 1) + j + 1];

    float dj  = d_dinv[tN + j];
    float acc = d_diag[tN + j] * dj * d_g[(size_t)node * ZD + k];
    int p = beg;
    for (; p + 4 <= end; p += 4) {
        int s0 = d_srcb[tE + p],     s1 = d_srcb[tE + p + 1];
        int s2 = d_srcb[tE + p + 2], s3 = d_srcb[tE + p + 3];
        float c0 = d_wb[tE + p]     * d_dinv[tN + s0];
        float c1 = d_wb[tE + p + 1] * d_dinv[tN + s1];
        float c2 = d_wb[tE + p + 2] * d_dinv[tN + s2];
        float c3 = d_wb[tE + p + 3] * d_dinv[tN + s3];
        float v0 = d_g[(size_t)(tN + s0) * ZD + k], v1 = d_g[(size_t)(tN + s1) * ZD + k];
        float v2 = d_g[(size_t)(tN + s2) * ZD + k], v3 = d_g[(size_t)(tN + s3) * ZD + k];
        acc = fmaf(c0, v0, acc); acc = fmaf(c1, v1, acc);
        acc = fmaf(c2, v2, acc); acc = fmaf(c3, v3, acc);
    }
    for (; p < end; p++) {
        int s = d_srcb[tE + p];
        acc = fmaf(d_wb[tE + p] * d_dinv[tN + s], d_g[(size_t)(tN + s) * ZD + k], acc);
    }
    out[(size_t)node * ZD + k] = tanhf(fmaf(acc, dj, b2[k]));
}

// ---------------- launch (2 memsets; gemm = slot 6 as verified in R3) --------
extern "C" void kernel_launch(void* const* d_in, const int* in_sizes, int n_in,
                              void* d_out, int out_size) {
    const float* x  = (const float*)d_in[0];
    const int*   ei = (const int*)d_in[1];
    const float* ew = (const float*)d_in[2];
    const float* W1 = (const float*)d_in[3];
    const float* b1 = (const float*)d_in[4];
    const float* W2 = (const float*)d_in[5];
    const float* b2 = (const float*)d_in[6];
    float* out = (float*)d_out;

    cudaFuncSetAttribute(gemm_kernel, cudaFuncAttributeMaxDynamicSharedMemorySize, GEMM_SMEM);

    void *pcnt = nullptr, *ph0 = nullptr;
    cudaGetSymbolAddress(&pcnt, d_cnt);
    cudaGetSymbolAddress(&ph0, d_h0);
    cudaMemsetAsync(ph0, 0, sizeof(float) * NN * HD);             // 1
    cudaMemsetAsync(pcnt, 0, sizeof(int) * TT * NN);              // 2

    detect_kernel<<<1, 32>>>(ei);                                 // 3
    hist_kernel<<<(TT * EE + 255) / 256, 256>>>(ei);              // 4
    scan_kernel<<<dim3(SCH, TT), 1024>>>();                       // 5
    gemm_kernel<<<dim3((NN + BMg - 1) / BMg, KSPLIT), 256, GEMM_SMEM>>>(x, W1);  // 6 (profiled)
    scatter_kernel<<<(TT * EE + 255) / 256, 256>>>(ei, ew);       // 7
    dedup_kernel<<<(TT * NN * 32 + 255) / 256, 256>>>();          // 8
    spmm1_kernel<<<(TT * NN * 32 + 255) / 256, 256>>>(b1, W2);    // 9
    spmm2_kernel<<<(TT * NN * 16 + 255) / 256, 256>>>(b2, out);   // 10
}

// round 7
// speedup vs baseline: 1.8608x; 1.0305x over previous
#include <cuda_runtime.h>
#include <cstdint>
#include <math.h>

#define NN 8746
#define KD 8746
#define HD 32
#define ZD 16
#define TT 6
#define EE 100000

// GEMM tiling: BM=128, BK=32, split-K x4 (grid 276 = single wave), 4-stage pipe
#define BMg 128
#define BKg 32
#define STg 4
#define KSPLIT 4
#define TPC 69                         // tiles per K-chunk (last chunk: 67)
#define NTILE_TOT 274                  // ceil(8746/32)
#define KDP (NTILE_TOT * BKg)          // 8768: W rows padded to tile boundary
#define XSTR 36                        // x row stride in floats
#define WSTR 40                        // W row stride in words
#define XTILE_BYTES (BMg * XSTR * 4)   // 18432
#define WTILE_BYTES (BKg * WSTR * 4)   // 5120
#define GEMM_SMEM (STg * (XTILE_BYTES + WTILE_BYTES))   // 94208

#define SCH 9                          // scan chunks per timestep

// ---------------- scratch (device globals; no allocations allowed) ----------
__device__ float    d_h0[NN * HD];
__device__ uint32_t d_w1t[KDP * HD];     // W1 pre-converted to tf32, zero-padded
__device__ int      d_cnt[TT * NN];
__device__ int      d_off[TT * (NN + 1)];
__device__ int      d_cur[TT * NN];
__device__ int      d_srcb[TT * EE];
__device__ int      d_eidb[TT * EE];
__device__ float    d_wb[TT * EE];
__device__ float    d_diag[TT * NN];
__device__ float    d_dinv[TT * NN];
__device__ float    d_g[TT * NN * ZD];

// ---------------- helpers ---------------------------------------------------
__device__ __forceinline__ void cp16(uint32_t dst, const void* src, int nb) {
    asm volatile("cp.async.cg.shared.global [%0], [%1], 16, %2;\n"
                 :: "r"(dst), "l"(src), "r"(nb) : "memory");
}
__device__ __forceinline__ uint32_t f2tf(float f) {
    uint32_t r;
    asm("cvt.rna.tf32.f32 %0, %1;" : "=r"(r) : "f"(f));
    return r;
}
__device__ __forceinline__ int ld_idx(const int* ei, int pos, int f) {
    return f ? ei[2 * pos] : ei[pos];
}
// inline int64-vs-int32 detection: hi words of first 5 int64 values are 0
__device__ __forceinline__ int i64_flag(const int* ei) {
    return ((ei[1] | ei[3] | ei[5] | ei[7] | ei[9]) == 0) ? 1 : 0;
}

// ---------------- W1 -> tf32 pre-convert (also zero-pads tail rows) ----------
__global__ void w1cvt_kernel(const float* __restrict__ W1) {
    int idx = blockIdx.x * 256 + threadIdx.x;
    if (idx >= KDP * HD) return;
    int k = idx >> 5;
    float v = (k < KD) ? W1[idx] : 0.f;
    d_w1t[idx] = f2tf(v);
}

// ---------------- GEMM: h0 += x @ W1 (tf32 mma, warp-coalesced cp.async) -----
__global__ void __launch_bounds__(256, 2)
gemm_kernel(const float* __restrict__ x) {
    extern __shared__ __align__(16) char smem[];
    float*    xs = (float*)smem;                            // [STg][BMg*XSTR]
    uint32_t* ws = (uint32_t*)(smem + STg * XTILE_BYTES);   // [STg][BKg*WSTR]

    const int tid  = threadIdx.x;
    const int lane = tid & 31;
    const int warp = tid >> 5;
    const int m0   = blockIdx.x * BMg;
    const int tile0 = blockIdx.y * TPC;
    const int ntile = min(TPC, NTILE_TOT - tile0);
    const int kbeg  = tile0 * BKg;
    const bool clampblk = (m0 + BMg > NN);
    const long XEND = (long)NN * KD;

    const uint32_t xs_u = (uint32_t)__cvta_generic_to_shared(xs);
    const uint32_t ws_u = (uint32_t)__cvta_generic_to_shared(ws);

    // x-copy: warp w owns rows [16w,16w+16) = 8 pairs, 17 16B chunks per pair
    long     xoff[5];
    uint32_t xdst[5];
    int      xok[5];
#pragma unroll
    for (int i = 0; i < 5; i++) {
        int q = i * 32 + lane;
        xok[i] = 0;
        if (q < 136) {
            int pair = q / 17, k = q - pair * 17;
            int odd  = (k >= 8) ? 1 : 0;
            int row  = warp * 16 + pair * 2 + odd;
            int cc   = odd ? (k - 8) : k;
            if (!(clampblk && row >= NN - m0)) {
                xoff[i] = (long)(m0 + row) * KD + kbeg + cc * 4 - (odd ? 2 : 0);
                xdst[i] = (uint32_t)(row * XSTR + cc * 4) * 4;
                xok[i]  = 1;
            }
        }
    }
    // W copy: 32 k-rows x 128B, lanes 0-7 cover one row contiguously; no predicate
    const int wkk = tid >> 3, wg = tid & 7;
    const uint32_t wdst = (uint32_t)(wkk * WSTR + wg * 4) * 4;

    auto load_tiles = [&](int buf, int tileIdx) {
        const uint32_t xb = xs_u + (uint32_t)buf * XTILE_BYTES;
#pragma unroll
        for (int i = 0; i < 5; i++) {
            if (xok[i]) {
                long o = xoff[i] + (long)tileIdx * BKg;
                int nb = 16;
                if (clampblk) {
                    long remB = (XEND - o) * 4;
                    if (remB < 16) { nb = remB > 0 ? (int)remB : 0; if (nb == 0) o = 0; }
                }
                cp16(xb + xdst[i], x + o, nb);
            }
        }
        {
            int gk = kbeg + tileIdx * BKg + wkk;     // < KDP always (padded)
            cp16(ws_u + (uint32_t)buf * WTILE_BYTES + wdst,
                 d_w1t + (long)gk * HD + wg * 4, 16);
        }
    };

#pragma unroll
    for (int s = 0; s < STg - 1; s++) {
        load_tiles(s, s);
        asm volatile("cp.async.commit_group;\n" ::: "memory");
    }

    float acc[4][4];
#pragma unroll
    for (int a = 0; a < 4; a++)
#pragma unroll
        for (int b = 0; b < 4; b++) acc[a][b] = 0.f;

    const int arow = warp * 16 + (lane >> 2);
    const int sh   = (arow & 1) ? 2 : 0;       // odd rows stored shifted by 2 floats
    const int kq   = lane & 3;
    const int qn   = lane >> 2;

    for (int it = 0; it < ntile; it++) {
        asm volatile("cp.async.wait_group %0;\n" :: "n"(STg - 2) : "memory");
        __syncthreads();

        if (it + STg - 1 < ntile)
            load_tiles((it + STg - 1) & 3, it + STg - 1);
        asm volatile("cp.async.commit_group;\n" ::: "memory");

        const float*    xb = xs + (it & 3) * (BMg * XSTR);
        const uint32_t* wb = ws + (it & 3) * (BKg * WSTR);
#pragma unroll
        for (int s = 0; s < 4; s++) {
            const int k8 = s * 8;
            uint32_t a0 = f2tf(xb[arow * XSTR + sh + k8 + kq]);
            uint32_t a1 = f2tf(xb[(arow + 8) * XSTR + sh + k8 + kq]);
            uint32_t a2 = f2tf(xb[arow * XSTR + sh + k8 + 4 + kq]);
            uint32_t a3 = f2tf(xb[(arow + 8) * XSTR + sh + k8 + 4 + kq]);
#pragma unroll
            for (int nt = 0; nt < 4; nt++) {
                uint32_t b0 = wb[(k8 + kq) * WSTR + nt * 8 + qn];       // pre-converted
                uint32_t b1 = wb[(k8 + 4 + kq) * WSTR + nt * 8 + qn];
                asm volatile(
                    "mma.sync.aligned.m16n8k8.row.col.f32.tf32.tf32.f32 "
                    "{%0,%1,%2,%3}, {%4,%5,%6,%7}, {%8,%9}, {%0,%1,%2,%3};\n"
                    : "+f"(acc[nt][0]), "+f"(acc[nt][1]), "+f"(acc[nt][2]), "+f"(acc[nt][3])
                    : "r"(a0), "r"(a1), "r"(a2), "r"(a3), "r"(b0), "r"(b1));
            }
        }
    }

    // split-K epilogue: atomic accumulate
    const int r0 = m0 + arow;
    const int r1 = r0 + 8;
    const int c0 = (lane & 3) * 2;
#pragma unroll
    for (int nt = 0; nt < 4; nt++) {
        int c = nt * 8 + c0;
        if (r0 < NN) {
            atomicAdd(&d_h0[r0 * HD + c],     acc[nt][0]);
            atomicAdd(&d_h0[r0 * HD + c + 1], acc[nt][1]);
        }
        if (r1 < NN) {
            atomicAdd(&d_h0[r1 * HD + c],     acc[nt][2]);
            atomicAdd(&d_h0[r1 * HD + c + 1], acc[nt][3]);
        }
    }
}

// ---------------- edge histogram --------------------------------------------
__global__ void hist_kernel(const int* __restrict__ ei) {
    int idx = blockIdx.x * 256 + threadIdx.x;
    if (idx >= TT * EE) return;
    int f = i64_flag(ei);
    int t = idx / EE, e = idx - t * EE;
    int j = ld_idx(ei, t * 2 * EE + EE + e, f);
    atomicAdd(&d_cnt[t * NN + j], 1);
}

// ---------------- scan: redundant prefix (no cross-block chain) --------------
__global__ void __launch_bounds__(1024) scan_kernel() {
    const int t   = blockIdx.y;
    const int ch  = blockIdx.x;
    const int tid = threadIdx.x;
    const int lane = tid & 31, w = tid >> 5;
    __shared__ int wsum[32];
    __shared__ int psum[32];

    int pre = 0;
    for (int i = tid; i < ch * 1024; i += 1024) pre += d_cnt[t * NN + i];

    int i = ch * 1024 + tid;
    int v = (i < NN) ? d_cnt[t * NN + i] : 0;

    int incl = v;
#pragma unroll
    for (int o = 1; o < 32; o <<= 1) {
        int u = __shfl_up_sync(0xffffffffu, incl, o);
        if (lane >= o) incl += u;
    }
#pragma unroll
    for (int o = 16; o; o >>= 1) pre += __shfl_xor_sync(0xffffffffu, pre, o);

    if (lane == 31) wsum[w] = incl;
    if (lane == 0)  psum[w] = pre;
    __syncthreads();
    if (w == 0) {
        int s = wsum[lane];
        int is = s;
#pragma unroll
        for (int o = 1; o < 32; o <<= 1) {
            int u = __shfl_up_sync(0xffffffffu, is, o);
            if (lane >= o) is += u;
        }
        wsum[lane] = is - s;
        int p = psum[lane];
#pragma unroll
        for (int o = 16; o; o >>= 1) p += __shfl_xor_sync(0xffffffffu, p, o);
        psum[lane] = p;
    }
    __syncthreads();

    int prev = psum[0];
    int blk_incl = wsum[w] + incl;

    if (i < NN) {
        int excl = prev + blk_incl - v;
        d_off[t * (NN + 1) + i] = excl;
        d_cur[t * NN + i]       = excl;
    }
    if (ch == SCH - 1 && tid == 1023)
        d_off[t * (NN + 1) + NN] = prev + blk_incl;
}

// ---------------- scatter edges into CSR -------------------------------------
__global__ void scatter_kernel(const int* __restrict__ ei, const float* __restrict__ ew) {
    int idx = blockIdx.x * 256 + threadIdx.x;
    if (idx >= TT * EE) return;
    int f = i64_flag(ei);
    int t = idx / EE, e = idx - t * EE;
    int i = ld_idx(ei, t * 2 * EE + e, f);
    int j = ld_idx(ei, t * 2 * EE + EE + e, f);
    int pos = atomicAdd(&d_cur[t * NN + j], 1);
    d_srcb[t * EE + pos] = i;
    d_eidb[t * EE + pos] = e;
    d_wb[t * EE + pos]   = ew[idx];
}

// ---------------- dedup (last edge index wins) + degrees ---------------------
__global__ void __launch_bounds__(256) dedup_kernel() {
    int gw   = (blockIdx.x * 256 + threadIdx.x) >> 5;
    int lane = threadIdx.x & 31;
    if (gw >= TT * NN) return;
    int t = gw / NN, j = gw - t * NN;
    int beg = d_off[t * (NN + 1) + j];
    int end = d_off[t * (NN + 1) + j + 1];

    float sum = 0.f;
    int selfw = 0;
    for (int p = beg + lane; p < end; p += 32) {
        int src = d_srcb[t * EE + p];
        int eid = d_eidb[t * EE + p];
        bool win = true;
        for (int q = beg; q < end; q++) {
            if (d_srcb[t * EE + q] == src && d_eidb[t * EE + q] > eid) { win = false; break; }
        }
        if (win) {
            sum += d_wb[t * EE + p];
            if (src == j) selfw = 1;
        } else {
            d_wb[t * EE + p] = 0.f;
        }
    }
#pragma unroll
    for (int o = 16; o; o >>= 1) {
        sum   += __shfl_xor_sync(0xffffffffu, sum, o);
        selfw |= __shfl_xor_sync(0xffffffffu, selfw, o);
    }
    if (lane == 0) {
        float diag = selfw ? 0.f : 1.f;
        d_diag[t * NN + j] = diag;
        d_dinv[t * NN + j] = rsqrtf(diag + sum);
    }
}

// ---------------- SpMM1 + ReLU + (h @ W2), p-loop unrolled x4 ----------------
__global__ void __launch_bounds__(256) spmm1_kernel(const float* __restrict__ b1,
                                                    const float* __restrict__ W2) {
    __shared__ float hs[8][HD];
    int gw   = (blockIdx.x * 256 + threadIdx.x) >> 5;
    int lane = threadIdx.x & 31;
    int wib  = (threadIdx.x >> 5);
    if (gw >= TT * NN) return;
    int t = gw / NN, j = gw - t * NN;
    const int tE = t * EE, tN = t * NN;
    int beg = d_off[t * (NN + 1) + j];
    int end = d_off[t * (NN + 1) + j + 1];

    float dj  = d_dinv[tN + j];
    float acc = d_diag[tN + j] * dj * d_h0[j * HD + lane];
    int p = beg;
    for (; p + 4 <= end; p += 4) {
        int s0 = d_srcb[tE + p],     s1 = d_srcb[tE + p + 1];
        int s2 = d_srcb[tE + p + 2], s3 = d_srcb[tE + p + 3];
        float c0 = d_wb[tE + p]     * d_dinv[tN + s0];
        float c1 = d_wb[tE + p + 1] * d_dinv[tN + s1];
        float c2 = d_wb[tE + p + 2] * d_dinv[tN + s2];
        float c3 = d_wb[tE + p + 3] * d_dinv[tN + s3];
        float v0 = d_h0[s0 * HD + lane], v1 = d_h0[s1 * HD + lane];
        float v2 = d_h0[s2 * HD + lane], v3 = d_h0[s3 * HD + lane];
        acc = fmaf(c0, v0, acc); acc = fmaf(c1, v1, acc);
        acc = fmaf(c2, v2, acc); acc = fmaf(c3, v3, acc);
    }
    for (; p < end; p++) {
        int s = d_srcb[tE + p];
        acc = fmaf(d_wb[tE + p] * d_dinv[tN + s], d_h0[s * HD + lane], acc);
    }
    float h = fmaxf(fmaf(acc, dj, b1[lane]), 0.f);
    hs[wib][lane] = h;
    __syncwarp();
    if (lane < ZD) {
        float s = 0.f;
#pragma unroll
        for (int c = 0; c < HD; c++) s = fmaf(hs[wib][c], W2[c * ZD + lane], s);
        d_g[(size_t)gw * ZD + lane] = s;
    }
}

// ---------------- SpMM2 + tanh (2 nodes/warp), p-loop unrolled x4 ------------
__global__ void __launch_bounds__(256) spmm2_kernel(const float* __restrict__ b2,
                                                    float* __restrict__ out) {
    int gwarp = (blockIdx.x * 256 + threadIdx.x) >> 5;
    int lane  = threadIdx.x & 31;
    int half  = lane >> 4, k = lane & 15;
    int node  = gwarp * 2 + half;
    if (node >= TT * NN) return;
    int t = node / NN, j = node - t * NN;
    const int tE = t * EE, tN = t * NN;
    int beg = d_off[t * (NN + 1) + j];
    int end = d_off[t * (NN + 1) + j + 1];

    float dj  = d_dinv[tN + j];
    float acc = d_diag[tN + j] * dj * d_g[(size_t)node * ZD + k];
    int p = beg;
    for (; p + 4 <= end; p += 4) {
        int s0 = d_srcb[tE + p],     s1 = d_srcb[tE + p + 1];
        int s2 = d_srcb[tE + p + 2], s3 = d_srcb[tE + p + 3];
        float c0 = d_wb[tE + p]     * d_dinv[tN + s0];
        float c1 = d_wb[tE + p + 1] * d_dinv[tN + s1];
        float c2 = d_wb[tE + p + 2] * d_dinv[tN + s2];
        float c3 = d_wb[tE + p + 3] * d_dinv[tN + s3];
        float v0 = d_g[(size_t)(tN + s0) * ZD + k], v1 = d_g[(size_t)(tN + s1) * ZD + k];
        float v2 = d_g[(size_t)(tN + s2) * ZD + k], v3 = d_g[(size_t)(tN + s3) * ZD + k];
        acc = fmaf(c0, v0, acc); acc = fmaf(c1, v1, acc);
        acc = fmaf(c2, v2, acc); acc = fmaf(c3, v3, acc);
    }
    for (; p < end; p++) {
        int s = d_srcb[tE + p];
        acc = fmaf(d_wb[tE + p] * d_dinv[tN + s], d_g[(size_t)(tN + s) * ZD + k], acc);
    }
    out[(size_t)node * ZD + k] = tanhf(fmaf(acc, dj, b2[k]));
}

// ---------------- launch (gemm = slot 6, w1cvt takes detect's slot 3) --------
extern "C" void kernel_launch(void* const* d_in, const int* in_sizes, int n_in,
                              void* d_out, int out_size) {
    const float* x  = (const float*)d_in[0];
    const int*   ei = (const int*)d_in[1];
    const float* ew = (const float*)d_in[2];
    const float* W1 = (const float*)d_in[3];
    const float* b1 = (const float*)d_in[4];
    const float* W2 = (const float*)d_in[5];
    const float* b2 = (const float*)d_in[6];
    float* out = (float*)d_out;

    cudaFuncSetAttribute(gemm_kernel, cudaFuncAttributeMaxDynamicSharedMemorySize, GEMM_SMEM);

    void *pcnt = nullptr, *ph0 = nullptr;
    cudaGetSymbolAddress(&pcnt, d_cnt);
    cudaGetSymbolAddress(&ph0, d_h0);
    cudaMemsetAsync(ph0, 0, sizeof(float) * NN * HD);                 // 1
    cudaMemsetAsync(pcnt, 0, sizeof(int) * TT * NN);                  // 2

    w1cvt_kernel<<<(KDP * HD + 255) / 256, 256>>>(W1);                // 3
    hist_kernel<<<(TT * EE + 255) / 256, 256>>>(ei);                  // 4
    scan_kernel<<<dim3(SCH, TT), 1024>>>();                           // 5
    gemm_kernel<<<dim3((NN + BMg - 1) / BMg, KSPLIT), 256, GEMM_SMEM>>>(x);  // 6 (profiled)
    scatter_kernel<<<(TT * EE + 255) / 256, 256>>>(ei, ew);           // 7
    dedup_kernel<<<(TT * NN * 32 + 255) / 256, 256>>>();              // 8
    spmm1_kernel<<<(TT * NN * 32 + 255) / 256, 256>>>(b1, W2);        // 9
    spmm2_kernel<<<(TT * NN * 16 + 255) / 256, 256>>>(b2, out);       // 10
}

// round 8
// speedup vs baseline: 1.9182x; 1.0308x over previous
#include <cuda_runtime.h>
#include <cstdint>
#include <math.h>

#define NN 8746
#define KD 8746
#define HD 32
#define ZD 16
#define TT 6
#define EE 100000

// GEMM tiling: BM=128, BK=32, split-K x4 (grid 276 = single wave), 4-stage pipe
#define BMg 128
#define BKg 32
#define STg 4
#define KSPLIT 4
#define TPC 69                         // tiles per K-chunk (last chunk: 67)
#define NTILE_TOT 274                  // ceil(8746/32)
#define KDP (NTILE_TOT * BKg)          // 8768
#define XSTR 36                        // x row stride in floats
#define XTILE_BYTES (BMg * XSTR * 4)   // 18432
#define WTILE_WORDS (BKg * HD)         // 1024 words = 4096 B, fragment-ordered
#define WTILE_BYTES (WTILE_WORDS * 4)
#define GEMM_SMEM (STg * (XTILE_BYTES + WTILE_BYTES))   // 90112

#define SCH 9                          // scan chunks per timestep

// ---------------- scratch (device globals; no allocations allowed) ----------
__device__ float    d_h0[NN * HD];
__device__ uint32_t d_w1t[NTILE_TOT * WTILE_WORDS];  // W1 tf32, MMA-fragment order
__device__ int      d_cnt[TT * NN];
__device__ int      d_off[TT * (NN + 1)];
__device__ int      d_cur[TT * NN];
__device__ int      d_srcb[TT * EE];
__device__ int      d_eidb[TT * EE];
__device__ float    d_wb[TT * EE];
__device__ float    d_diag[TT * NN];
__device__ float    d_dinv[TT * NN];
__device__ float    d_g[TT * NN * ZD];

// ---------------- helpers ---------------------------------------------------
__device__ __forceinline__ void cp16(uint32_t dst, const void* src, int nb) {
    asm volatile("cp.async.cg.shared.global [%0], [%1], 16, %2;\n"
                 :: "r"(dst), "l"(src), "r"(nb) : "memory");
}
__device__ __forceinline__ uint32_t f2tf(float f) {
    uint32_t r;
    asm("cvt.rna.tf32.f32 %0, %1;" : "=r"(r) : "f"(f));
    return r;
}
__device__ __forceinline__ int ld_idx(const int* ei, int pos, int f) {
    return f ? ei[2 * pos] : ei[pos];
}
__device__ __forceinline__ int i64_flag(const int* ei) {
    return ((ei[1] | ei[3] | ei[5] | ei[7] | ei[9]) == 0) ? 1 : 0;
}

// ---------------- W1 -> tf32, MMA-fragment-ordered ---------------------------
// word idx layout: [kt][s][half][lane][j]
//   value = tf32( W1[ kt*32 + s*8 + (lane&3) + half*4 ][ (lane>>2) + j*8 ] )
// so in-tile, lane l's b0 quad (nt=0..3) is one aligned float4 at s*256 + l*4,
// and its b1 quad at s*256 + 128 + l*4. Zero-padded past KD.
__global__ void w1cvt_kernel(const float* __restrict__ W1) {
    int idx = blockIdx.x * 256 + threadIdx.x;
    if (idx >= NTILE_TOT * WTILE_WORDS) return;
    int kt = idx >> 10, r = idx & 1023;
    int s = r >> 8, r2 = r & 255;
    int half = (r2 >> 7) & 1;
    int l = (r2 >> 2) & 31;
    int j = r2 & 3;
    int k = kt * 32 + s * 8 + (l & 3) + half * 4;
    int n = (l >> 2) + j * 8;
    d_w1t[idx] = (k < KD) ? f2tf(W1[k * HD + n]) : 0u;
}

// ---------------- GEMM: h0 += x @ W1 (tf32 mma, raw-bit A, vector B) ---------
__global__ void __launch_bounds__(256, 2)
gemm_kernel(const float* __restrict__ x) {
    extern __shared__ __align__(16) char smem[];
    float*    xs = (float*)smem;                            // [STg][BMg*XSTR]
    uint32_t* ws = (uint32_t*)(smem + STg * XTILE_BYTES);   // [STg][WTILE_WORDS]

    const int tid  = threadIdx.x;
    const int lane = tid & 31;
    const int warp = tid >> 5;
    const int m0   = blockIdx.x * BMg;
    const int tile0 = blockIdx.y * TPC;
    const int ntile = min(TPC, NTILE_TOT - tile0);
    const bool clampblk = (m0 + BMg > NN);
    const long XEND = (long)NN * KD;

    const uint32_t xs_u = (uint32_t)__cvta_generic_to_shared(xs);
    const uint32_t ws_u = (uint32_t)__cvta_generic_to_shared(ws);

    // x-copy: warp w owns rows [16w,16w+16) = 8 pairs, 17 16B chunks per pair
    long     xoff[5];
    uint32_t xdst[5];
    int      xok[5];
#pragma unroll
    for (int i = 0; i < 5; i++) {
        int q = i * 32 + lane;
        xok[i] = 0;
        if (q < 136) {
            int pair = q / 17, k = q - pair * 17;
            int odd  = (k >= 8) ? 1 : 0;
            int row  = warp * 16 + pair * 2 + odd;
            int cc   = odd ? (k - 8) : k;
            if (!(clampblk && row >= NN - m0)) {
                xoff[i] = (long)(m0 + row) * KD + tile0 * BKg + cc * 4 - (odd ? 2 : 0);
                xdst[i] = (uint32_t)(row * XSTR + cc * 4) * 4;
                xok[i]  = 1;
            }
        }
    }

    auto load_tiles = [&](int buf, int tileIdx) {
        const uint32_t xb = xs_u + (uint32_t)buf * XTILE_BYTES;
#pragma unroll
        for (int i = 0; i < 5; i++) {
            if (xok[i]) {
                long o = xoff[i] + (long)tileIdx * BKg;
                int nb = 16;
                if (clampblk) {
                    long remB = (XEND - o) * 4;
                    if (remB < 16) { nb = remB > 0 ? (int)remB : 0; if (nb == 0) o = 0; }
                }
                cp16(xb + xdst[i], x + o, nb);
            }
        }
        // W tile: 4KB fully contiguous, one 16B chunk per thread
        cp16(ws_u + (uint32_t)buf * WTILE_BYTES + (uint32_t)tid * 16,
             d_w1t + (long)(tile0 + tileIdx) * WTILE_WORDS + tid * 4, 16);
    };

#pragma unroll
    for (int s = 0; s < STg - 1; s++) {
        load_tiles(s, s);
        asm volatile("cp.async.commit_group;\n" ::: "memory");
    }

    float acc[4][4];
#pragma unroll
    for (int a = 0; a < 4; a++)
#pragma unroll
        for (int b = 0; b < 4; b++) acc[a][b] = 0.f;

    const int arow = warp * 16 + (lane >> 2);
    const int sh   = (arow & 1) ? 2 : 0;       // odd rows stored shifted by 2 floats
    const int kq   = lane & 3;

    for (int it = 0; it < ntile; it++) {
        asm volatile("cp.async.wait_group %0;\n" :: "n"(STg - 2) : "memory");
        __syncthreads();

        if (it + STg - 1 < ntile)
            load_tiles((it + STg - 1) & 3, it + STg - 1);
        asm volatile("cp.async.commit_group;\n" ::: "memory");

        const float*    xb = xs + (it & 3) * (BMg * XSTR);
        const uint32_t* wb = ws + (it & 3) * WTILE_WORDS;
#pragma unroll
        for (int s = 0; s < 4; s++) {
            const int k8 = s * 8;
            // A operand: raw fp32 bits = tf32 round-toward-zero (no CVT)
            uint32_t a0 = __float_as_uint(xb[arow * XSTR + sh + k8 + kq]);
            uint32_t a1 = __float_as_uint(xb[(arow + 8) * XSTR + sh + k8 + kq]);
            uint32_t a2 = __float_as_uint(xb[arow * XSTR + sh + k8 + 4 + kq]);
            uint32_t a3 = __float_as_uint(xb[(arow + 8) * XSTR + sh + k8 + 4 + kq]);
            // B operand: fragment-ordered, 2 conflict-free LDS.128
            uint4 va = *(const uint4*)(wb + s * 256 + lane * 4);
            uint4 vb = *(const uint4*)(wb + s * 256 + 128 + lane * 4);
            const uint32_t* b0q = &va.x;
            const uint32_t* b1q = &vb.x;
#pragma unroll
            for (int nt = 0; nt < 4; nt++) {
                asm volatile(
                    "mma.sync.aligned.m16n8k8.row.col.f32.tf32.tf32.f32 "
                    "{%0,%1,%2,%3}, {%4,%5,%6,%7}, {%8,%9}, {%0,%1,%2,%3};\n"
                    : "+f"(acc[nt][0]), "+f"(acc[nt][1]), "+f"(acc[nt][2]), "+f"(acc[nt][3])
                    : "r"(a0), "r"(a1), "r"(a2), "r"(a3), "r"(b0q[nt]), "r"(b1q[nt]));
            }
        }
    }

    // split-K epilogue: atomic accumulate
    const int r0 = m0 + arow;
    const int r1 = r0 + 8;
    const int c0 = (lane & 3) * 2;
#pragma unroll
    for (int nt = 0; nt < 4; nt++) {
        int c = nt * 8 + c0;
        if (r0 < NN) {
            atomicAdd(&d_h0[r0 * HD + c],     acc[nt][0]);
            atomicAdd(&d_h0[r0 * HD + c + 1], acc[nt][1]);
        }
        if (r1 < NN) {
            atomicAdd(&d_h0[r1 * HD + c],     acc[nt][2]);
            atomicAdd(&d_h0[r1 * HD + c + 1], acc[nt][3]);
        }
    }
}

// ---------------- edge histogram --------------------------------------------
__global__ void hist_kernel(const int* __restrict__ ei) {
    int idx = blockIdx.x * 256 + threadIdx.x;
    if (idx >= TT * EE) return;
    int f = i64_flag(ei);
    int t = idx / EE, e = idx - t * EE;
    int j = ld_idx(ei, t * 2 * EE + EE + e, f);
    atomicAdd(&d_cnt[t * NN + j], 1);
}

// ---------------- scan: redundant prefix (no cross-block chain) --------------
__global__ void __launch_bounds__(1024) scan_kernel() {
    const int t   = blockIdx.y;
    const int ch  = blockIdx.x;
    const int tid = threadIdx.x;
    const int lane = tid & 31, w = tid >> 5;
    __shared__ int wsum[32];
    __shared__ int psum[32];

    int pre = 0;
    for (int i = tid; i < ch * 1024; i += 1024) pre += d_cnt[t * NN + i];

    int i = ch * 1024 + tid;
    int v = (i < NN) ? d_cnt[t * NN + i] : 0;

    int incl = v;
#pragma unroll
    for (int o = 1; o < 32; o <<= 1) {
        int u = __shfl_up_sync(0xffffffffu, incl, o);
        if (lane >= o) incl += u;
    }
#pragma unroll
    for (int o = 16; o; o >>= 1) pre += __shfl_xor_sync(0xffffffffu, pre, o);

    if (lane == 31) wsum[w] = incl;
    if (lane == 0)  psum[w] = pre;
    __syncthreads();
    if (w == 0) {
        int s = wsum[lane];
        int is = s;
#pragma unroll
        for (int o = 1; o < 32; o <<= 1) {
            int u = __shfl_up_sync(0xffffffffu, is, o);
            if (lane >= o) is += u;
        }
        wsum[lane] = is - s;
        int p = psum[lane];
#pragma unroll
        for (int o = 16; o; o >>= 1) p += __shfl_xor_sync(0xffffffffu, p, o);
        psum[lane] = p;
    }
    __syncthreads();

    int prev = psum[0];
    int blk_incl = wsum[w] + incl;

    if (i < NN) {
        int excl = prev + blk_incl - v;
        d_off[t * (NN + 1) + i] = excl;
        d_cur[t * NN + i]       = excl;
    }
    if (ch == SCH - 1 && tid == 1023)
        d_off[t * (NN + 1) + NN] = prev + blk_incl;
}

// ---------------- scatter edges into CSR -------------------------------------
__global__ void scatter_kernel(const int* __restrict__ ei, const float* __restrict__ ew) {
    int idx = blockIdx.x * 256 + threadIdx.x;
    if (idx >= TT * EE) return;
    int f = i64_flag(ei);
    int t = idx / EE, e = idx - t * EE;
    int i = ld_idx(ei, t * 2 * EE + e, f);
    int j = ld_idx(ei, t * 2 * EE + EE + e, f);
    int pos = atomicAdd(&d_cur[t * NN + j], 1);
    d_srcb[t * EE + pos] = i;
    d_eidb[t * EE + pos] = e;
    d_wb[t * EE + pos]   = ew[idx];
}

// ---------------- dedup (last edge index wins) + degrees ---------------------
__global__ void __launch_bounds__(256) dedup_kernel() {
    int gw   = (blockIdx.x * 256 + threadIdx.x) >> 5;
    int lane = threadIdx.x & 31;
    if (gw >= TT * NN) return;
    int t = gw / NN, j = gw - t * NN;
    int beg = d_off[t * (NN + 1) + j];
    int end = d_off[t * (NN + 1) + j + 1];

    float sum = 0.f;
    int selfw = 0;
    for (int p = beg + lane; p < end; p += 32) {
        int src = d_srcb[t * EE + p];
        int eid = d_eidb[t * EE + p];
        bool win = true;
        for (int q = beg; q < end; q++) {
            if (d_srcb[t * EE + q] == src && d_eidb[t * EE + q] > eid) { win = false; break; }
        }
        if (win) {
            sum += d_wb[t * EE + p];
            if (src == j) selfw = 1;
        } else {
            d_wb[t * EE + p] = 0.f;
        }
    }
#pragma unroll
    for (int o = 16; o; o >>= 1) {
        sum   += __shfl_xor_sync(0xffffffffu, sum, o);
        selfw |= __shfl_xor_sync(0xffffffffu, selfw, o);
    }
    if (lane == 0) {
        float diag = selfw ? 0.f : 1.f;
        d_diag[t * NN + j] = diag;
        d_dinv[t * NN + j] = rsqrtf(diag + sum);
    }
}

// ---------------- SpMM1 + ReLU + (h @ W2), p-loop unrolled x4 ----------------
__global__ void __launch_bounds__(256) spmm1_kernel(const float* __restrict__ b1,
                                                    const float* __restrict__ W2) {
    __shared__ float hs[8][HD];
    int gw   = (blockIdx.x * 256 + threadIdx.x) >> 5;
    int lane = threadIdx.x & 31;
    int wib  = (threadIdx.x >> 5);
    if (gw >= TT * NN) return;
    int t = gw / NN, j = gw - t * NN;
    const int tE = t * EE, tN = t * NN;
    int beg = d_off[t * (NN + 1) + j];
    int end = d_off[t * (NN + 1) + j + 1];

    float dj  = d_dinv[tN + j];
    float acc = d_diag[tN + j] * dj * d_h0[j * HD + lane];
    int p = beg;
    for (; p + 4 <= end; p += 4) {
        int s0 = d_srcb[tE + p],     s1 = d_srcb[tE + p + 1];
        int s2 = d_srcb[tE + p + 2], s3 = d_srcb[tE + p + 3];
        float c0 = d_wb[tE + p]     * d_dinv[tN + s0];
        float c1 = d_wb[tE + p + 1] * d_dinv[tN + s1];
        float c2 = d_wb[tE + p + 2] * d_dinv[tN + s2];
        float c3 = d_wb[tE + p + 3] * d_dinv[tN + s3];
        float v0 = d_h0[s0 * HD + lane], v1 = d_h0[s1 * HD + lane];
        float v2 = d_h0[s2 * HD + lane], v3 = d_h0[s3 * HD + lane];
        acc = fmaf(c0, v0, acc); acc = fmaf(c1, v1, acc);
        acc = fmaf(c2, v2, acc); acc = fmaf(c3, v3, acc);
    }
    for (; p < end; p++) {
        int s = d_srcb[tE + p];
        acc = fmaf(d_wb[tE + p] * d_dinv[tN + s], d_h0[s * HD + lane], acc);
    }
    float h = fmaxf(fmaf(acc, dj, b1[lane]), 0.f);
    hs[wib][lane] = h;
    __syncwarp();
    if (lane < ZD) {
        float s = 0.f;
#pragma unroll
        for (int c = 0; c < HD; c++) s = fmaf(hs[wib][c], W2[c * ZD + lane], s);
        d_g[(size_t)gw * ZD + lane] = s;
    }
}

// ---------------- SpMM2 + tanh (2 nodes/warp), p-loop unrolled x4 ------------
__global__ void __launch_bounds__(256) spmm2_kernel(const float* __restrict__ b2,
                                                    float* __restrict__ out) {
    int gwarp = (blockIdx.x * 256 + threadIdx.x) >> 5;
    int lane  = threadIdx.x & 31;
    int half  = lane >> 4, k = lane & 15;
    int node  = gwarp * 2 + half;
    if (node >= TT * NN) return;
    int t = node / NN, j = node - t * NN;
    const int tE = t * EE, tN = t * NN;
    int beg = d_off[t * (NN + 1) + j];
    int end = d_off[t * (NN + 1) + j + 1];

    float dj  = d_dinv[tN + j];
    float acc = d_diag[tN + j] * dj * d_g[(size_t)node * ZD + k];
    int p = beg;
    for (; p + 4 <= end; p += 4) {
        int s0 = d_srcb[tE + p],     s1 = d_srcb[tE + p + 1];
        int s2 = d_srcb[tE + p + 2], s3 = d_srcb[tE + p + 3];
        float c0 = d_wb[tE + p]     * d_dinv[tN + s0];
        float c1 = d_wb[tE + p + 1] * d_dinv[tN + s1];
        float c2 = d_wb[tE + p + 2] * d_dinv[tN + s2];
        float c3 = d_wb[tE + p + 3] * d_dinv[tN + s3];
        float v0 = d_g[(size_t)(tN + s0) * ZD + k], v1 = d_g[(size_t)(tN + s1) * ZD + k];
        float v2 = d_g[(size_t)(tN + s2) * ZD + k], v3 = d_g[(size_t)(tN + s3) * ZD + k];
        acc = fmaf(c0, v0, acc); acc = fmaf(c1, v1, acc);
        acc = fmaf(c2, v2, acc); acc = fmaf(c3, v3, acc);
    }
    for (; p < end; p++) {
        int s = d_srcb[tE + p];
        acc = fmaf(d_wb[tE + p] * d_dinv[tN + s], d_g[(size_t)(tN + s) * ZD + k], acc);
    }
    out[(size_t)node * ZD + k] = tanhf(fmaf(acc, dj, b2[k]));
}

// ---------------- launch (gemm = slot 6) --------------------------------------
extern "C" void kernel_launch(void* const* d_in, const int* in_sizes, int n_in,
                              void* d_out, int out_size) {
    const float* x  = (const float*)d_in[0];
    const int*   ei = (const int*)d_in[1];
    const float* ew = (const float*)d_in[2];
    const float* W1 = (const float*)d_in[3];
    const float* b1 = (const float*)d_in[4];
    const float* W2 = (const float*)d_in[5];
    const float* b2 = (const float*)d_in[6];
    float* out = (float*)d_out;

    cudaFuncSetAttribute(gemm_kernel, cudaFuncAttributeMaxDynamicSharedMemorySize, GEMM_SMEM);

    void *pcnt = nullptr, *ph0 = nullptr;
    cudaGetSymbolAddress(&pcnt, d_cnt);
    cudaGetSymbolAddress(&ph0, d_h0);
    cudaMemsetAsync(ph0, 0, sizeof(float) * NN * HD);                 // 1
    cudaMemsetAsync(pcnt, 0, sizeof(int) * TT * NN);                  // 2

    w1cvt_kernel<<<(NTILE_TOT * WTILE_WORDS + 255) / 256, 256>>>(W1); // 3
    hist_kernel<<<(TT * EE + 255) / 256, 256>>>(ei);                  // 4
    scan_kernel<<<dim3(SCH, TT), 1024>>>();                           // 5
    gemm_kernel<<<dim3((NN + BMg - 1) / BMg, KSPLIT), 256, GEMM_SMEM>>>(x);  // 6 (profiled)
    scatter_kernel<<<(TT * EE + 255) / 256, 256>>>(ei, ew);           // 7
    dedup_kernel<<<(TT * NN * 32 + 255) / 256, 256>>>();              // 8
    spmm1_kernel<<<(TT * NN * 32 + 255) / 256, 256>>>(b1, W2);        // 9
    spmm2_kernel<<<(TT * NN * 16 + 255) / 256, 256>>>(b2, out);       // 10
}

// round 9
// speedup vs baseline: 1.9375x; 1.0101x over previous
#include <cuda_runtime.h>
#include <cstdint>
#include <math.h>

#define NN 8746
#define KD 8746
#define HD 32
#define ZD 16
#define TT 6
#define EE 100000

// GEMM tiling: BM=128, BK=32, split-K x6 (grid 414, 3 blocks/SM), 3-stage pipe
#define BMg 128
#define BKg 32
#define STg 3
#define KSPLIT 6
#define TPC 46                         // tiles per K-chunk (last chunk: 44)
#define NTILE_TOT 274                  // ceil(8746/32)
#define XSTR 36                        // x row stride in floats
#define XTILE_BYTES (BMg * XSTR * 4)   // 18432
#define WTILE_WORDS (BKg * HD)         // 1024 words = 4096 B, fragment-ordered
#define WTILE_BYTES (WTILE_WORDS * 4)
#define GEMM_SMEM (STg * (XTILE_BYTES + WTILE_BYTES))   // 67584

#define SCH 9                          // scan chunks per timestep

// ---------------- scratch (device globals; no allocations allowed) ----------
__device__ float    d_h0[NN * HD];
__device__ uint32_t d_w1t[NTILE_TOT * WTILE_WORDS];  // W1 tf32, MMA-fragment order
__device__ int      d_cnt[TT * NN];
__device__ int      d_off[TT * (NN + 1)];
__device__ int      d_cur[TT * NN];
__device__ int      d_srcb[TT * EE];
__device__ int      d_eidb[TT * EE];
__device__ float    d_wb[TT * EE];
__device__ float    d_diag[TT * NN];
__device__ float    d_dinv[TT * NN];
__device__ float    d_g[TT * NN * ZD];

// ---------------- helpers ---------------------------------------------------
__device__ __forceinline__ void cp16(uint32_t dst, const void* src, int nb) {
    asm volatile("cp.async.cg.shared.global [%0], [%1], 16, %2;\n"
                 :: "r"(dst), "l"(src), "r"(nb) : "memory");
}
__device__ __forceinline__ uint32_t f2tf(float f) {
    uint32_t r;
    asm("cvt.rna.tf32.f32 %0, %1;" : "=r"(r) : "f"(f));
    return r;
}
__device__ __forceinline__ int ld_idx(const int* ei, int pos, int f) {
    return f ? ei[2 * pos] : ei[pos];
}
__device__ __forceinline__ int i64_flag(const int* ei) {
    return ((ei[1] | ei[3] | ei[5] | ei[7] | ei[9]) == 0) ? 1 : 0;
}

// ---------------- W1 -> tf32, MMA-fragment-ordered ---------------------------
// word idx layout: [kt][s][half][lane][j]
//   value = tf32( W1[ kt*32 + s*8 + (lane&3) + half*4 ][ (lane>>2) + j*8 ] )
__global__ void w1cvt_kernel(const float* __restrict__ W1) {
    int idx = blockIdx.x * 256 + threadIdx.x;
    if (idx >= NTILE_TOT * WTILE_WORDS) return;
    int kt = idx >> 10, r = idx & 1023;
    int s = r >> 8, r2 = r & 255;
    int half = (r2 >> 7) & 1;
    int l = (r2 >> 2) & 31;
    int j = r2 & 3;
    int k = kt * 32 + s * 8 + (l & 3) + half * 4;
    int n = (l >> 2) + j * 8;
    d_w1t[idx] = (k < KD) ? f2tf(W1[k * HD + n]) : 0u;
}

// ---------------- GEMM: h0 += x @ W1 (tf32 mma, raw-bit A, vector B) ---------
__global__ void __launch_bounds__(256, 3)
gemm_kernel(const float* __restrict__ x) {
    extern __shared__ __align__(16) char smem[];
    float*    xs = (float*)smem;                            // [STg][BMg*XSTR]
    uint32_t* ws = (uint32_t*)(smem + STg * XTILE_BYTES);   // [STg][WTILE_WORDS]

    const int tid  = threadIdx.x;
    const int lane = tid & 31;
    const int warp = tid >> 5;
    const int m0   = blockIdx.x * BMg;
    const int tile0 = blockIdx.y * TPC;
    const int ntile = min(TPC, NTILE_TOT - tile0);
    const bool clampblk = (m0 + BMg > NN);
    const char* xbase = (const char*)x;
    const uint32_t XENDB = (uint32_t)((long)NN * KD * 4);   // 306MB < 4GB

    const uint32_t xs_u = (uint32_t)__cvta_generic_to_shared(xs);
    const uint32_t ws_u = (uint32_t)__cvta_generic_to_shared(ws);

    // x-copy: warp w owns rows [16w,16w+16) = 8 pairs, 17 16B chunks per pair.
    // Offsets are 32-bit bytes, advanced incrementally by 128B per tile.
    uint32_t xoff[5];
    uint32_t xdst[5];
    int      xok[5];
#pragma unroll
    for (int i = 0; i < 5; i++) {
        int q = i * 32 + lane;
        xok[i] = 0;
        xoff[i] = 0;
        if (q < 136) {
            int pair = q / 17, k = q - pair * 17;
            int odd  = (k >= 8) ? 1 : 0;
            int row  = warp * 16 + pair * 2 + odd;
            int cc   = odd ? (k - 8) : k;
            if (!(clampblk && row >= NN - m0)) {
                xoff[i] = (uint32_t)(((long)(m0 + row) * KD + tile0 * BKg + cc * 4
                                      - (odd ? 2 : 0)) * 4);
                xdst[i] = (uint32_t)(row * XSTR + cc * 4) * 4;
                xok[i]  = 1;
            }
        }
    }
    // W tile source: contiguous, advanced by 4KB per tile
    const char* wsrc = (const char*)d_w1t + (long)tile0 * WTILE_BYTES + tid * 16;

    auto load_tiles = [&](int buf) {
        const uint32_t xb = xs_u + (uint32_t)buf * XTILE_BYTES;
#pragma unroll
        for (int i = 0; i < 5; i++) {
            if (xok[i]) {
                uint32_t o = xoff[i];
                int nb = 16;
                if (clampblk) {
                    if (o >= XENDB) { nb = 0; o = 0; }
                    else if (XENDB - o < 16) nb = (int)(XENDB - o);
                }
                cp16(xb + xdst[i], xbase + o, nb);
                xoff[i] += BKg * 4;
            }
        }
        cp16(ws_u + (uint32_t)buf * WTILE_BYTES + (uint32_t)tid * 16, wsrc, 16);
        wsrc += WTILE_BYTES;
    };

#pragma unroll
    for (int s = 0; s < STg - 1; s++) {
        load_tiles(s);
        asm volatile("cp.async.commit_group;\n" ::: "memory");
    }

    float acc[4][4];
#pragma unroll
    for (int a = 0; a < 4; a++)
#pragma unroll
        for (int b = 0; b < 4; b++) acc[a][b] = 0.f;

    const int arow = warp * 16 + (lane >> 2);
    const int sh   = (arow & 1) ? 2 : 0;       // odd rows stored shifted by 2 floats
    const int kq   = lane & 3;

    int cbuf = 0, lbuf = STg - 1;              // compute / load buffer cursors
    for (int it = 0; it < ntile; it++) {
        asm volatile("cp.async.wait_group %0;\n" :: "n"(STg - 2) : "memory");
        __syncthreads();

        if (it + STg - 1 < ntile)
            load_tiles(lbuf);
        asm volatile("cp.async.commit_group;\n" ::: "memory");
        lbuf = (lbuf == STg - 1) ? 0 : lbuf + 1;

        const float*    xb = xs + cbuf * (BMg * XSTR);
        const uint32_t* wb = ws + cbuf * WTILE_WORDS;
        cbuf = (cbuf == STg - 1) ? 0 : cbuf + 1;
#pragma unroll
        for (int s = 0; s < 4; s++) {
            const int k8 = s * 8;
            // A operand: raw fp32 bits = tf32 round-toward-zero (no CVT)
            uint32_t a0 = __float_as_uint(xb[arow * XSTR + sh + k8 + kq]);
            uint32_t a1 = __float_as_uint(xb[(arow + 8) * XSTR + sh + k8 + kq]);
            uint32_t a2 = __float_as_uint(xb[arow * XSTR + sh + k8 + 4 + kq]);
            uint32_t a3 = __float_as_uint(xb[(arow + 8) * XSTR + sh + k8 + 4 + kq]);
            // B operand: fragment-ordered, 2 conflict-free LDS.128
            uint4 va = *(const uint4*)(wb + s * 256 + lane * 4);
            uint4 vb = *(const uint4*)(wb + s * 256 + 128 + lane * 4);
            const uint32_t* b0q = &va.x;
            const uint32_t* b1q = &vb.x;
#pragma unroll
            for (int nt = 0; nt < 4; nt++) {
                asm volatile(
                    "mma.sync.aligned.m16n8k8.row.col.f32.tf32.tf32.f32 "
                    "{%0,%1,%2,%3}, {%4,%5,%6,%7}, {%8,%9}, {%0,%1,%2,%3};\n"
                    : "+f"(acc[nt][0]), "+f"(acc[nt][1]), "+f"(acc[nt][2]), "+f"(acc[nt][3])
                    : "r"(a0), "r"(a1), "r"(a2), "r"(a3), "r"(b0q[nt]), "r"(b1q[nt]));
            }
        }
    }

    // split-K epilogue: atomic accumulate
    const int r0 = m0 + arow;
    const int r1 = r0 + 8;
    const int c0 = (lane & 3) * 2;
#pragma unroll
    for (int nt = 0; nt < 4; nt++) {
        int c = nt * 8 + c0;
        if (r0 < NN) {
            atomicAdd(&d_h0[r0 * HD + c],     acc[nt][0]);
            atomicAdd(&d_h0[r0 * HD + c + 1], acc[nt][1]);
        }
        if (r1 < NN) {
            atomicAdd(&d_h0[r1 * HD + c],     acc[nt][2]);
            atomicAdd(&d_h0[r1 * HD + c + 1], acc[nt][3]);
        }
    }
}

// ---------------- edge histogram --------------------------------------------
__global__ void hist_kernel(const int* __restrict__ ei) {
    int idx = blockIdx.x * 256 + threadIdx.x;
    if (idx >= TT * EE) return;
    int f = i64_flag(ei);
    int t = idx / EE, e = idx - t * EE;
    int j = ld_idx(ei, t * 2 * EE + EE + e, f);
    atomicAdd(&d_cnt[t * NN + j], 1);
}

// ---------------- scan: redundant prefix (no cross-block chain) --------------
__global__ void __launch_bounds__(1024) scan_kernel() {
    const int t   = blockIdx.y;
    const int ch  = blockIdx.x;
    const int tid = threadIdx.x;
    const int lane = tid & 31, w = tid >> 5;
    __shared__ int wsum[32];
    __shared__ int psum[32];

    int pre = 0;
    for (int i = tid; i < ch * 1024; i += 1024) pre += d_cnt[t * NN + i];

    int i = ch * 1024 + tid;
    int v = (i < NN) ? d_cnt[t * NN + i] : 0;

    int incl = v;
#pragma unroll
    for (int o = 1; o < 32; o <<= 1) {
        int u = __shfl_up_sync(0xffffffffu, incl, o);
        if (lane >= o) incl += u;
    }
#pragma unroll
    for (int o = 16; o; o >>= 1) pre += __shfl_xor_sync(0xffffffffu, pre, o);

    if (lane == 31) wsum[w] = incl;
    if (lane == 0)  psum[w] = pre;
    __syncthreads();
    if (w == 0) {
        int s = wsum[lane];
        int is = s;
#pragma unroll
        for (int o = 1; o < 32; o <<= 1) {
            int u = __shfl_up_sync(0xffffffffu, is, o);
            if (lane >= o) is += u;
        }
        wsum[lane] = is - s;
        int p = psum[lane];
#pragma unroll
        for (int o = 16; o; o >>= 1) p += __shfl_xor_sync(0xffffffffu, p, o);
        psum[lane] = p;
    }
    __syncthreads();

    int prev = psum[0];
    int blk_incl = wsum[w] + incl;

    if (i < NN) {
        int excl = prev + blk_incl - v;
        d_off[t * (NN + 1) + i] = excl;
        d_cur[t * NN + i]       = excl;
    }
    if (ch == SCH - 1 && tid == 1023)
        d_off[t * (NN + 1) + NN] = prev + blk_incl;
}

// ---------------- scatter edges into CSR -------------------------------------
__global__ void scatter_kernel(const int* __restrict__ ei, const float* __restrict__ ew) {
    int idx = blockIdx.x * 256 + threadIdx.x;
    if (idx >= TT * EE) return;
    int f = i64_flag(ei);
    int t = idx / EE, e = idx - t * EE;
    int i = ld_idx(ei, t * 2 * EE + e, f);
    int j = ld_idx(ei, t * 2 * EE + EE + e, f);
    int pos = atomicAdd(&d_cur[t * NN + j], 1);
    d_srcb[t * EE + pos] = i;
    d_eidb[t * EE + pos] = e;
    d_wb[t * EE + pos]   = ew[idx];
}

// ---------------- dedup (last edge index wins) + degrees ---------------------
__global__ void __launch_bounds__(256) dedup_kernel() {
    int gw   = (blockIdx.x * 256 + threadIdx.x) >> 5;
    int lane = threadIdx.x & 31;
    if (gw >= TT * NN) return;
    int t = gw / NN, j = gw - t * NN;
    int beg = d_off[t * (NN + 1) + j];
    int end = d_off[t * (NN + 1) + j + 1];

    float sum = 0.f;
    int selfw = 0;
    for (int p = beg + lane; p < end; p += 32) {
        int src = d_srcb[t * EE + p];
        int eid = d_eidb[t * EE + p];
        bool win = true;
        for (int q = beg; q < end; q++) {
            if (d_srcb[t * EE + q] == src && d_eidb[t * EE + q] > eid) { win = false; break; }
        }
        if (win) {
            sum += d_wb[t * EE + p];
            if (src == j) selfw = 1;
        } else {
            d_wb[t * EE + p] = 0.f;
        }
    }
#pragma unroll
    for (int o = 16; o; o >>= 1) {
        sum   += __shfl_xor_sync(0xffffffffu, sum, o);
        selfw |= __shfl_xor_sync(0xffffffffu, selfw, o);
    }
    if (lane == 0) {
        float diag = selfw ? 0.f : 1.f;
        d_diag[t * NN + j] = diag;
        d_dinv[t * NN + j] = rsqrtf(diag + sum);
    }
}

// ---------------- SpMM1 + ReLU + (h @ W2), p-loop unrolled x4 ----------------
__global__ void __launch_bounds__(256) spmm1_kernel(const float* __restrict__ b1,
                                                    const float* __restrict__ W2) {
    __shared__ float hs[8][HD];
    int gw   = (blockIdx.x * 256 + threadIdx.x) >> 5;
    int lane = threadIdx.x & 31;
    int wib  = (threadIdx.x >> 5);
    if (gw >= TT * NN) return;
    int t = gw / NN, j = gw - t * NN;
    const int tE = t * EE, tN = t * NN;
    int beg = d_off[t * (NN + 1) + j];
    int end = d_off[t * (NN + 1) + j + 1];

    float dj  = d_dinv[tN + j];
    float acc = d_diag[tN + j] * dj * d_h0[j * HD + lane];
    int p = beg;
    for (; p + 4 <= end; p += 4) {
        int s0 = d_srcb[tE + p],     s1 = d_srcb[tE + p + 1];
        int s2 = d_srcb[tE + p + 2], s3 = d_srcb[tE + p + 3];
        float c0 = d_wb[tE + p]     * d_dinv[tN + s0];
        float c1 = d_wb[tE + p + 1] * d_dinv[tN + s1];
        float c2 = d_wb[tE + p + 2] * d_dinv[tN + s2];
        float c3 = d_wb[tE + p + 3] * d_dinv[tN + s3];
        float v0 = d_h0[s0 * HD + lane], v1 = d_h0[s1 * HD + lane];
        float v2 = d_h0[s2 * HD + lane], v3 = d_h0[s3 * HD + lane];
        acc = fmaf(c0, v0, acc); acc = fmaf(c1, v1, acc);
        acc = fmaf(c2, v2, acc); acc = fmaf(c3, v3, acc);
    }
    for (; p < end; p++) {
        int s = d_srcb[tE + p];
        acc = fmaf(d_wb[tE + p] * d_dinv[tN + s], d_h0[s * HD + lane], acc);
    }
    float h = fmaxf(fmaf(acc, dj, b1[lane]), 0.f);
    hs[wib][lane] = h;
    __syncwarp();
    if (lane < ZD) {
        float s = 0.f;
#pragma unroll
        for (int c = 0; c < HD; c++) s = fmaf(hs[wib][c], W2[c * ZD + lane], s);
        d_g[(size_t)gw * ZD + lane] = s;
    }
}

// ---------------- SpMM2 + tanh (2 nodes/warp), p-loop unrolled x4 ------------
__global__ void __launch_bounds__(256) spmm2_kernel(const float* __restrict__ b2,
                                                    float* __restrict__ out) {
    int gwarp = (blockIdx.x * 256 + threadIdx.x) >> 5;
    int lane  = threadIdx.x & 31;
    int half  = lane >> 4, k = lane & 15;
    int node  = gwarp * 2 + half;
    if (node >= TT * NN) return;
    int t = node / NN, j = node - t * NN;
    const int tE = t * EE, tN = t * NN;
    int beg = d_off[t * (NN + 1) + j];
    int end = d_off[t * (NN + 1) + j + 1];

    float dj  = d_dinv[tN + j];
    float acc = d_diag[tN + j] * dj * d_g[(size_t)node * ZD + k];
    int p = beg;
    for (; p + 4 <= end; p += 4) {
        int s0 = d_srcb[tE + p],     s1 = d_srcb[tE + p + 1];
        int s2 = d_srcb[tE + p + 2], s3 = d_srcb[tE + p + 3];
        float c0 = d_wb[tE + p]     * d_dinv[tN + s0];
        float c1 = d_wb[tE + p + 1] * d_dinv[tN + s1];
        float c2 = d_wb[tE + p + 2] * d_dinv[tN + s2];
        float c3 = d_wb[tE + p + 3] * d_dinv[tN + s3];
        float v0 = d_g[(size_t)(tN + s0) * ZD + k], v1 = d_g[(size_t)(tN + s1) * ZD + k];
        float v2 = d_g[(size_t)(tN + s2) * ZD + k], v3 = d_g[(size_t)(tN + s3) * ZD + k];
        acc = fmaf(c0, v0, acc); acc = fmaf(c1, v1, acc);
        acc = fmaf(c2, v2, acc); acc = fmaf(c3, v3, acc);
    }
    for (; p < end; p++) {
        int s = d_srcb[tE + p];
        acc = fmaf(d_wb[tE + p] * d_dinv[tN + s], d_g[(size_t)(tN + s) * ZD + k], acc);
    }
    out[(size_t)node * ZD + k] = tanhf(fmaf(acc, dj, b2[k]));
}

// ---------------- launch (gemm = slot 6) --------------------------------------
extern "C" void kernel_launch(void* const* d_in, const int* in_sizes, int n_in,
                              void* d_out, int out_size) {
    const float* x  = (const float*)d_in[0];
    const int*   ei = (const int*)d_in[1];
    const float* ew = (const float*)d_in[2];
    const float* W1 = (const float*)d_in[3];
    const float* b1 = (const float*)d_in[4];
    const float* W2 = (const float*)d_in[5];
    const float* b2 = (const float*)d_in[6];
    float* out = (float*)d_out;

    cudaFuncSetAttribute(gemm_kernel, cudaFuncAttributeMaxDynamicSharedMemorySize, GEMM_SMEM);

    void *pcnt = nullptr, *ph0 = nullptr;
    cudaGetSymbolAddress(&pcnt, d_cnt);
    cudaGetSymbolAddress(&ph0, d_h0);
    cudaMemsetAsync(ph0, 0, sizeof(float) * NN * HD);                 // 1
    cudaMemsetAsync(pcnt, 0, sizeof(int) * TT * NN);                  // 2

    w1cvt_kernel<<<(NTILE_TOT * WTILE_WORDS + 255) / 256, 256>>>(W1); // 3
    hist_kernel<<<(TT * EE + 255) / 256, 256>>>(ei);                  // 4
    scan_kernel<<<dim3(SCH, TT), 1024>>>();                           // 5
    gemm_kernel<<<dim3((NN + BMg - 1) / BMg, KSPLIT), 256, GEMM_SMEM>>>(x);  // 6 (profiled)
    scatter_kernel<<<(TT * EE + 255) / 256, 256>>>(ei, ew);           // 7
    dedup_kernel<<<(TT * NN * 32 + 255) / 256, 256>>>();              // 8
    spmm1_kernel<<<(TT * NN * 32 + 255) / 256, 256>>>(b1, W2);        // 9
    spmm2_kernel<<<(TT * NN * 16 + 255) / 256, 256>>>(b2, out);       // 10
}

// round 10
// speedup vs baseline: 2.0600x; 1.0632x over previous
#include <cuda_runtime.h>
#include <cstdint>
#include <math.h>

#define NN 8746
#define KD 8746
#define HD 32
#define ZD 16
#define TT 6
#define EE 100000

// GEMM tiling: BM=128, BK=32, split-K x6 (grid 414, 3 blocks/SM), 3-stage pipe
#define BMg 128
#define BKg 32
#define STg 3
#define KSPLIT 6
#define TPC 46
#define NTILE_TOT 274
#define XSTR 36
#define XTILE_BYTES (BMg * XSTR * 4)
#define WTILE_WORDS (BKg * HD)
#define WTILE_BYTES (WTILE_WORDS * 4)
#define GEMM_SMEM (STg * (XTILE_BYTES + WTILE_BYTES))   // 67584

#define SCH 9

// ---------------- scratch (device globals; no allocations allowed) ----------
__device__ float    d_h0[NN * HD];
__device__ uint32_t d_w1t[NTILE_TOT * WTILE_WORDS];
__device__ int      d_cnt[TT * NN];
__device__ int      d_off[TT * (NN + 1)];
__device__ int      d_cur[TT * NN];
__device__ unsigned long long d_se[TT * EE];   // packed (eid<<32)|src
__device__ float    d_wb[TT * EE];
__device__ float    d_diag[TT * NN];
__device__ float    d_dinv[TT * NN];
__device__ float    d_g[TT * NN * ZD];

// ---------------- helpers ---------------------------------------------------
__device__ __forceinline__ void cp16(uint32_t dst, const void* src, int nb) {
    asm volatile("cp.async.cg.shared.global [%0], [%1], 16, %2;\n"
                 :: "r"(dst), "l"(src), "r"(nb) : "memory");
}
__device__ __forceinline__ uint32_t f2tf(float f) {
    uint32_t r;
    asm("cvt.rna.tf32.f32 %0, %1;" : "=r"(r) : "f"(f));
    return r;
}
__device__ __forceinline__ int ld_idx(const int* ei, int pos, int f) {
    return f ? ei[2 * pos] : ei[pos];
}
__device__ __forceinline__ int i64_flag(const int* ei) {
    return ((ei[1] | ei[3] | ei[5] | ei[7] | ei[9]) == 0) ? 1 : 0;
}

// ---------------- fused prep: zero h0 + zero cnt + W1->tf32 fragment layout --
#define PREP_H0 (NN * HD)                         // 279872
#define PREP_CNT (TT * NN)                        // 52476
#define PREP_W1 (NTILE_TOT * WTILE_WORDS)         // 280576
#define PREP_TOT (PREP_H0 + PREP_CNT + PREP_W1)
__global__ void prep_kernel(const float* __restrict__ W1) {
    int idx = blockIdx.x * 256 + threadIdx.x;
    if (idx < PREP_H0) {
        d_h0[idx] = 0.f;
    } else if (idx < PREP_H0 + PREP_CNT) {
        d_cnt[idx - PREP_H0] = 0;
    } else if (idx < PREP_TOT) {
        int w = idx - PREP_H0 - PREP_CNT;
        int kt = w >> 10, r = w & 1023;
        int s = r >> 8, r2 = r & 255;
        int half = (r2 >> 7) & 1;
        int l = (r2 >> 2) & 31;
        int j = r2 & 3;
        int k = kt * 32 + s * 8 + (l & 3) + half * 4;
        int n = (l >> 2) + j * 8;
        d_w1t[w] = (k < KD) ? f2tf(W1[k * HD + n]) : 0u;
    }
}

// ---------------- edge histogram --------------------------------------------
__global__ void hist_kernel(const int* __restrict__ ei) {
    int idx = blockIdx.x * 256 + threadIdx.x;
    if (idx >= TT * EE) return;
    int f = i64_flag(ei);
    int t = idx / EE, e = idx - t * EE;
    int j = ld_idx(ei, t * 2 * EE + EE + e, f);
    atomicAdd(&d_cnt[t * NN + j], 1);
}

// ---------------- scan: redundant prefix -------------------------------------
__global__ void __launch_bounds__(1024) scan_kernel() {
    const int t   = blockIdx.y;
    const int ch  = blockIdx.x;
    const int tid = threadIdx.x;
    const int lane = tid & 31, w = tid >> 5;
    __shared__ int wsum[32];
    __shared__ int psum[32];

    int pre = 0;
    for (int i = tid; i < ch * 1024; i += 1024) pre += d_cnt[t * NN + i];

    int i = ch * 1024 + tid;
    int v = (i < NN) ? d_cnt[t * NN + i] : 0;

    int incl = v;
#pragma unroll
    for (int o = 1; o < 32; o <<= 1) {
        int u = __shfl_up_sync(0xffffffffu, incl, o);
        if (lane >= o) incl += u;
    }
#pragma unroll
    for (int o = 16; o; o >>= 1) pre += __shfl_xor_sync(0xffffffffu, pre, o);

    if (lane == 31) wsum[w] = incl;
    if (lane == 0)  psum[w] = pre;
    __syncthreads();
    if (w == 0) {
        int s = wsum[lane];
        int is = s;
#pragma unroll
        for (int o = 1; o < 32; o <<= 1) {
            int u = __shfl_up_sync(0xffffffffu, is, o);
            if (lane >= o) is += u;
        }
        wsum[lane] = is - s;
        int p = psum[lane];
#pragma unroll
        for (int o = 16; o; o >>= 1) p += __shfl_xor_sync(0xffffffffu, p, o);
        psum[lane] = p;
    }
    __syncthreads();

    int prev = psum[0];
    int blk_incl = wsum[w] + incl;

    if (i < NN) {
        int excl = prev + blk_incl - v;
        d_off[t * (NN + 1) + i] = excl;
        d_cur[t * NN + i]       = excl;
    }
    if (ch == SCH - 1 && tid == 1023)
        d_off[t * (NN + 1) + NN] = prev + blk_incl;
}

// ---------------- GEMM: h0 += x @ W1 (tf32 mma, raw-bit A, vector B) ---------
__global__ void __launch_bounds__(256, 3)
gemm_kernel(const float* __restrict__ x) {
    extern __shared__ __align__(16) char smem[];
    float*    xs = (float*)smem;
    uint32_t* ws = (uint32_t*)(smem + STg * XTILE_BYTES);

    const int tid  = threadIdx.x;
    const int lane = tid & 31;
    const int warp = tid >> 5;
    const int m0   = blockIdx.x * BMg;
    const int tile0 = blockIdx.y * TPC;
    const int ntile = min(TPC, NTILE_TOT - tile0);
    const bool clampblk = (m0 + BMg > NN);
    const char* xbase = (const char*)x;
    const uint32_t XENDB = (uint32_t)((long)NN * KD * 4);

    const uint32_t xs_u = (uint32_t)__cvta_generic_to_shared(xs);
    const uint32_t ws_u = (uint32_t)__cvta_generic_to_shared(ws);

    uint32_t xoff[5];
    uint32_t xdst[5];
    int      xok[5];
#pragma unroll
    for (int i = 0; i < 5; i++) {
        int q = i * 32 + lane;
        xok[i] = 0;
        xoff[i] = 0;
        if (q < 136) {
            int pair = q / 17, k = q - pair * 17;
            int odd  = (k >= 8) ? 1 : 0;
            int row  = warp * 16 + pair * 2 + odd;
            int cc   = odd ? (k - 8) : k;
            if (!(clampblk && row >= NN - m0)) {
                xoff[i] = (uint32_t)(((long)(m0 + row) * KD + tile0 * BKg + cc * 4
                                      - (odd ? 2 : 0)) * 4);
                xdst[i] = (uint32_t)(row * XSTR + cc * 4) * 4;
                xok[i]  = 1;
            }
        }
    }
    const char* wsrc = (const char*)d_w1t + (long)tile0 * WTILE_BYTES + tid * 16;

    auto load_tiles = [&](int buf) {
        const uint32_t xb = xs_u + (uint32_t)buf * XTILE_BYTES;
#pragma unroll
        for (int i = 0; i < 5; i++) {
            if (xok[i]) {
                uint32_t o = xoff[i];
                int nb = 16;
                if (clampblk) {
                    if (o >= XENDB) { nb = 0; o = 0; }
                    else if (XENDB - o < 16) nb = (int)(XENDB - o);
                }
                cp16(xb + xdst[i], xbase + o, nb);
                xoff[i] += BKg * 4;
            }
        }
        cp16(ws_u + (uint32_t)buf * WTILE_BYTES + (uint32_t)tid * 16, wsrc, 16);
        wsrc += WTILE_BYTES;
    };

#pragma unroll
    for (int s = 0; s < STg - 1; s++) {
        load_tiles(s);
        asm volatile("cp.async.commit_group;\n" ::: "memory");
    }

    float acc[4][4];
#pragma unroll
    for (int a = 0; a < 4; a++)
#pragma unroll
        for (int b = 0; b < 4; b++) acc[a][b] = 0.f;

    const int arow = warp * 16 + (lane >> 2);
    const int sh   = (arow & 1) ? 2 : 0;
    const int kq   = lane & 3;

    int cbuf = 0, lbuf = STg - 1;
    for (int it = 0; it < ntile; it++) {
        asm volatile("cp.async.wait_group %0;\n" :: "n"(STg - 2) : "memory");
        __syncthreads();

        if (it + STg - 1 < ntile)
            load_tiles(lbuf);
        asm volatile("cp.async.commit_group;\n" ::: "memory");
        lbuf = (lbuf == STg - 1) ? 0 : lbuf + 1;

        const float*    xb = xs + cbuf * (BMg * XSTR);
        const uint32_t* wb = ws + cbuf * WTILE_WORDS;
        cbuf = (cbuf == STg - 1) ? 0 : cbuf + 1;
#pragma unroll
        for (int s = 0; s < 4; s++) {
            const int k8 = s * 8;
            uint32_t a0 = __float_as_uint(xb[arow * XSTR + sh + k8 + kq]);
            uint32_t a1 = __float_as_uint(xb[(arow + 8) * XSTR + sh + k8 + kq]);
            uint32_t a2 = __float_as_uint(xb[arow * XSTR + sh + k8 + 4 + kq]);
            uint32_t a3 = __float_as_uint(xb[(arow + 8) * XSTR + sh + k8 + 4 + kq]);
            uint4 va = *(const uint4*)(wb + s * 256 + lane * 4);
            uint4 vb = *(const uint4*)(wb + s * 256 + 128 + lane * 4);
            const uint32_t* b0q = &va.x;
            const uint32_t* b1q = &vb.x;
#pragma unroll
            for (int nt = 0; nt < 4; nt++) {
                asm volatile(
                    "mma.sync.aligned.m16n8k8.row.col.f32.tf32.tf32.f32 "
                    "{%0,%1,%2,%3}, {%4,%5,%6,%7}, {%8,%9}, {%0,%1,%2,%3};\n"
                    : "+f"(acc[nt][0]), "+f"(acc[nt][1]), "+f"(acc[nt][2]), "+f"(acc[nt][3])
                    : "r"(a0), "r"(a1), "r"(a2), "r"(a3), "r"(b0q[nt]), "r"(b1q[nt]));
            }
        }
    }

    const int r0 = m0 + arow;
    const int r1 = r0 + 8;
    const int c0 = (lane & 3) * 2;
#pragma unroll
    for (int nt = 0; nt < 4; nt++) {
        int c = nt * 8 + c0;
        if (r0 < NN) {
            atomicAdd(&d_h0[r0 * HD + c],     acc[nt][0]);
            atomicAdd(&d_h0[r0 * HD + c + 1], acc[nt][1]);
        }
        if (r1 < NN) {
            atomicAdd(&d_h0[r1 * HD + c],     acc[nt][2]);
            atomicAdd(&d_h0[r1 * HD + c + 1], acc[nt][3]);
        }
    }
}

// ---------------- scatter edges into CSR (packed (eid<<32)|src) --------------
__global__ void scatter_kernel(const int* __restrict__ ei, const float* __restrict__ ew) {
    int idx = blockIdx.x * 256 + threadIdx.x;
    if (idx >= TT * EE) return;
    int f = i64_flag(ei);
    int t = idx / EE, e = idx - t * EE;
    int i = ld_idx(ei, t * 2 * EE + e, f);
    int j = ld_idx(ei, t * 2 * EE + EE + e, f);
    int pos = atomicAdd(&d_cur[t * NN + j], 1);
    d_se[t * EE + pos] = ((unsigned long long)(unsigned)e << 32) | (unsigned)i;
    d_wb[t * EE + pos] = ew[idx];
}

// ---------------- dedup: warp-shuffle fast path (deg <= 32) ------------------
__global__ void __launch_bounds__(256) dedup_kernel() {
    int gw   = (blockIdx.x * 256 + threadIdx.x) >> 5;
    int lane = threadIdx.x & 31;
    if (gw >= TT * NN) return;
    int t = gw / NN, j = gw - t * NN;
    int beg = d_off[t * (NN + 1) + j];
    int end = d_off[t * (NN + 1) + j + 1];
    int deg = end - beg;

    float sum = 0.f;
    int selfw = 0;

    if (deg <= 32) {
        // fast path: whole segment lives in warp registers
        unsigned long long pk = 0; float w = 0.f; int active = (lane < deg);
        if (active) { pk = d_se[t * EE + beg + lane]; w = d_wb[t * EE + beg + lane]; }
        int win = active;
        for (int q = 0; q < deg; q++) {
            unsigned long long oq = __shfl_sync(0xffffffffu, pk, q);
            if (active && q != lane &&
                (unsigned)oq == (unsigned)pk && oq > pk) win = 0;
        }
        if (active) {
            if (win) {
                sum = w;
                if ((int)(unsigned)pk == j) selfw = 1;
            } else {
                d_wb[t * EE + beg + lane] = 0.f;
            }
        }
    } else {
        // slow path (degree > 32): global rescan
        for (int p = beg + lane; p < end; p += 32) {
            unsigned long long pk = d_se[t * EE + p];
            bool win = true;
            for (int q = beg; q < end; q++) {
                unsigned long long oq = d_se[t * EE + q];
                if (q != p && (unsigned)oq == (unsigned)pk && oq > pk) { win = false; break; }
            }
            if (win) {
                sum += d_wb[t * EE + p];
                if ((int)(unsigned)pk == j) selfw = 1;
            } else {
                d_wb[t * EE + p] = 0.f;
            }
        }
    }
#pragma unroll
    for (int o = 16; o; o >>= 1) {
        sum   += __shfl_xor_sync(0xffffffffu, sum, o);
        selfw |= __shfl_xor_sync(0xffffffffu, selfw, o);
    }
    if (lane == 0) {
        float diag = selfw ? 0.f : 1.f;
        d_diag[t * NN + j] = diag;
        d_dinv[t * NN + j] = rsqrtf(diag + sum);
    }
}

// ---------------- SpMM1 + ReLU + (h @ W2), p-loop unrolled x4 ----------------
__global__ void __launch_bounds__(256) spmm1_kernel(const float* __restrict__ b1,
                                                    const float* __restrict__ W2) {
    __shared__ float hs[8][HD];
    int gw   = (blockIdx.x * 256 + threadIdx.x) >> 5;
    int lane = threadIdx.x & 31;
    int wib  = (threadIdx.x >> 5);
    if (gw >= TT * NN) return;
    int t = gw / NN, j = gw - t * NN;
    const int tE = t * EE, tN = t * NN;
    int beg = d_off[t * (NN + 1) + j];
    int end = d_off[t * (NN + 1) + j + 1];

    float dj  = d_dinv[tN + j];
    float acc = d_diag[tN + j] * dj * d_h0[j * HD + lane];
    int p = beg;
    for (; p + 4 <= end; p += 4) {
        int s0 = (int)(unsigned)d_se[tE + p];
        int s1 = (int)(unsigned)d_se[tE + p + 1];
        int s2 = (int)(unsigned)d_se[tE + p + 2];
        int s3 = (int)(unsigned)d_se[tE + p + 3];
        float c0 = d_wb[tE + p]     * d_dinv[tN + s0];
        float c1 = d_wb[tE + p + 1] * d_dinv[tN + s1];
        float c2 = d_wb[tE + p + 2] * d_dinv[tN + s2];
        float c3 = d_wb[tE + p + 3] * d_dinv[tN + s3];
        float v0 = d_h0[s0 * HD + lane], v1 = d_h0[s1 * HD + lane];
        float v2 = d_h0[s2 * HD + lane], v3 = d_h0[s3 * HD + lane];
        acc = fmaf(c0, v0, acc); acc = fmaf(c1, v1, acc);
        acc = fmaf(c2, v2, acc); acc = fmaf(c3, v3, acc);
    }
    for (; p < end; p++) {
        int s = (int)(unsigned)d_se[tE + p];
        acc = fmaf(d_wb[tE + p] * d_dinv[tN + s], d_h0[s * HD + lane], acc);
    }
    float h = fmaxf(fmaf(acc, dj, b1[lane]), 0.f);
    hs[wib][lane] = h;
    __syncwarp();
    if (lane < ZD) {
        float s = 0.f;
#pragma unroll
        for (int c = 0; c < HD; c++) s = fmaf(hs[wib][c], W2[c * ZD + lane], s);
        d_g[(size_t)gw * ZD + lane] = s;
    }
}

// ---------------- SpMM2 + tanh (2 nodes/warp), p-loop unrolled x4 ------------
__global__ void __launch_bounds__(256) spmm2_kernel(const float* __restrict__ b2,
                                                    float* __restrict__ out) {
    int gwarp = (blockIdx.x * 256 + threadIdx.x) >> 5;
    int lane  = threadIdx.x & 31;
    int half  = lane >> 4, k = lane & 15;
    int node  = gwarp * 2 + half;
    if (node >= TT * NN) return;
    int t = node / NN, j = node - t * NN;
    const int tE = t * EE, tN = t * NN;
    int beg = d_off[t * (NN + 1) + j];
    int end = d_off[t * (NN + 1) + j + 1];

    float dj  = d_dinv[tN + j];
    float acc = d_diag[tN + j] * dj * d_g[(size_t)node * ZD + k];
    int p = beg;
    for (; p + 4 <= end; p += 4) {
        int s0 = (int)(unsigned)d_se[tE + p];
        int s1 = (int)(unsigned)d_se[tE + p + 1];
        int s2 = (int)(unsigned)d_se[tE + p + 2];
        int s3 = (int)(unsigned)d_se[tE + p + 3];
        float c0 = d_wb[tE + p]     * d_dinv[tN + s0];
        float c1 = d_wb[tE + p + 1] * d_dinv[tN + s1];
        float c2 = d_wb[tE + p + 2] * d_dinv[tN + s2];
        float c3 = d_wb[tE + p + 3] * d_dinv[tN + s3];
        float v0 = d_g[(size_t)(tN + s0) * ZD + k], v1 = d_g[(size_t)(tN + s1) * ZD + k];
        float v2 = d_g[(size_t)(tN + s2) * ZD + k], v3 = d_g[(size_t)(tN + s3) * ZD + k];
        acc = fmaf(c0, v0, acc); acc = fmaf(c1, v1, acc);
        acc = fmaf(c2, v2, acc); acc = fmaf(c3, v3, acc);
    }
    for (; p < end; p++) {
        int s = (int)(unsigned)d_se[tE + p];
        acc = fmaf(d_wb[tE + p] * d_dinv[tN + s], d_g[(size_t)(tN + s) * ZD + k], acc);
    }
    out[(size_t)node * ZD + k] = tanhf(fmaf(acc, dj, b2[k]));
}

// ---------------- launch (8 launches; dedup = profiled slot 6) ---------------
extern "C" void kernel_launch(void* const* d_in, const int* in_sizes, int n_in,
                              void* d_out, int out_size) {
    const float* x  = (const float*)d_in[0];
    const int*   ei = (const int*)d_in[1];
    const float* ew = (const float*)d_in[2];
    const float* W1 = (const float*)d_in[3];
    const float* b1 = (const float*)d_in[4];
    const float* W2 = (const float*)d_in[5];
    const float* b2 = (const float*)d_in[6];
    float* out = (float*)d_out;

    cudaFuncSetAttribute(gemm_kernel, cudaFuncAttributeMaxDynamicSharedMemorySize, GEMM_SMEM);

    prep_kernel<<<(PREP_TOT + 255) / 256, 256>>>(W1);                 // 1
    hist_kernel<<<(TT * EE + 255) / 256, 256>>>(ei);                  // 2
    scan_kernel<<<dim3(SCH, TT), 1024>>>();                           // 3
    gemm_kernel<<<dim3((NN + BMg - 1) / BMg, KSPLIT), 256, GEMM_SMEM>>>(x);  // 4
    scatter_kernel<<<(TT * EE + 255) / 256, 256>>>(ei, ew);           // 5
    dedup_kernel<<<(TT * NN * 32 + 255) / 256, 256>>>();              // 6 (profiled)
    spmm1_kernel<<<(TT * NN * 32 + 255) / 256, 256>>>(b1, W2);        // 7
    spmm2_kernel<<<(TT * NN * 16 + 255) / 256, 256>>>(b2, out);       // 8
}